// round 6
// baseline (speedup 1.0000x reference)
#include <cuda_runtime.h>
#include <cuda_bf16.h>
#include <cstdint>

#define NODES 50
#define EPG   400
#define NGRAPH 512
#define NN    (NGRAPH*NODES)   // 25600
#define NE    (NGRAPH*EPG)     // 204800
#define FDIM  512
#define HEADS 8
#define CH    64
#define NA    5
#define GRUH  128
#define GRUI  1024
#define G3    384

// ---------------- scratch (static device globals; no allocation) ----------------
__device__ float g_bufA[NN*FDIM];
__device__ float g_bufB[NN*FDIM];
__device__ __nv_bfloat16 g_Ah[NN*FDIM];
__device__ __nv_bfloat16 g_Al[NN*FDIM];
__device__ __nv_bfloat16 g_Bh[GRUI*G3 > FDIM*FDIM ? GRUI*G3 : FDIM*FDIM];
__device__ __nv_bfloat16 g_Bl[GRUI*G3 > FDIM*FDIM ? GRUI*G3 : FDIM*FDIM];
__device__ float g_GI[NGRAPH*NA*G3];
__device__ float g_gruout[NGRAPH*NA*GRUH];

// ---------------- helpers ----------------
__device__ __forceinline__ uint32_t smem_u32(const void* p) {
    uint32_t a;
    asm("{ .reg .u64 t; cvta.to.shared.u64 t, %1; cvt.u32.u64 %0, t; }" : "=r"(a) : "l"(p));
    return a;
}
__device__ __forceinline__ void cp16(uint32_t sdst, const void* gsrc) {
    asm volatile("cp.async.cg.shared.global [%0], [%1], 16;" :: "r"(sdst), "l"(gsrc) : "memory");
}
__device__ __forceinline__ uint32_t lds32(uint32_t a) {
    uint32_t v;
    asm volatile("ld.shared.b32 %0, [%1];" : "=r"(v) : "r"(a));
    return v;
}
__device__ __forceinline__ void mma16816(float* c, uint32_t a0, uint32_t a1,
                                         uint32_t a2, uint32_t a3,
                                         uint32_t b0, uint32_t b1) {
    asm volatile(
        "mma.sync.aligned.m16n8k16.row.col.f32.bf16.bf16.f32 "
        "{%0,%1,%2,%3}, {%4,%5,%6,%7}, {%8,%9}, {%0,%1,%2,%3};"
        : "+f"(c[0]), "+f"(c[1]), "+f"(c[2]), "+f"(c[3])
        : "r"(a0), "r"(a1), "r"(a2), "r"(a3), "r"(b0), "r"(b1));
}
__device__ __forceinline__ void split1(float v, __nv_bfloat16& h, __nv_bfloat16& l) {
    h = __float2bfloat16_rn(v);
    l = __float2bfloat16_rn(v - __bfloat162float(h));
}

// W [K,N] fp32 -> Wt [N,K] bf16 hi/lo (transposed)
__global__ void splitT_k(const float* __restrict__ W, __nv_bfloat16* __restrict__ hi,
                         __nv_bfloat16* __restrict__ lo, int K, int N) {
    int idx = blockIdx.x * 256 + threadIdx.x;
    if (idx >= N * K) return;
    int n = idx / K, k = idx - n * K;
    float v = W[(size_t)k * N + n];
    __nv_bfloat16 h, l;
    split1(v, h, l);
    hi[idx] = h;
    lo[idx] = l;
}

// ---------------- HMMA bf16-split GEMM: C[M,N] = A[M,K] * B[N,K]^T ----------------
#define STAGES 3
#define PITCH 80
#define MAT_BYTES (128*PITCH)
#define STAGE_BYTES (4*MAT_BYTES)
#define GEMM_SMEM (STAGES*STAGE_BYTES)

__global__ void __launch_bounds__(256) gemm_mma(
    const __nv_bfloat16* __restrict__ Ah, const __nv_bfloat16* __restrict__ Al,
    const __nv_bfloat16* __restrict__ Bh, const __nv_bfloat16* __restrict__ Bl,
    float* __restrict__ C, int M, int N, int K) {
    extern __shared__ char sm8[];
    const uint32_t sb = smem_u32(sm8);
    const int tid = threadIdx.x;
    const int lane = tid & 31, wid = tid >> 5;
    const int wm = wid & 3, wn = wid >> 2;
    const int bm = blockIdx.y * 128, bn = blockIdx.x * 128;
    const int g = lane >> 2, tig = lane & 3;
    const int NCH = K >> 5;

    const char* pAh = (const char*)Ah;
    const char* pAl = (const char*)Al;
    const char* pBh = (const char*)Bh;
    const char* pBl = (const char*)Bl;
    const size_t rowb = (size_t)K * 2;

    auto load_stage = [&](int kc, int s) {
        uint32_t sbase = sb + s * STAGE_BYTES;
        size_t kb = (size_t)kc * 64;
#pragma unroll
        for (int i = tid; i < 512; i += 256) {
            int r = i >> 2, gg = i & 3;
            uint32_t so = sbase + r * PITCH + gg * 16;
            size_t ga = (size_t)(bm + r) * rowb + kb + gg * 16;
            size_t gb = (size_t)(bn + r) * rowb + kb + gg * 16;
            cp16(so,                 pAh + ga);
            cp16(so + MAT_BYTES,     pAl + ga);
            cp16(so + 2*MAT_BYTES,   pBh + gb);
            cp16(so + 3*MAT_BYTES,   pBl + gb);
        }
        asm volatile("cp.async.commit_group;" ::: "memory");
    };

    float acc[2][8][4];
#pragma unroll
    for (int f = 0; f < 2; f++)
#pragma unroll
        for (int nf = 0; nf < 8; nf++)
#pragma unroll
            for (int c = 0; c < 4; c++) acc[f][nf][c] = 0.f;

    load_stage(0, 0);
    load_stage(1, 1);

    for (int kc = 0; kc < NCH; kc++) {
        int s = kc % STAGES;
        asm volatile("cp.async.wait_group 1;" ::: "memory");
        __syncthreads();
        if (kc + 2 < NCH) load_stage(kc + 2, (kc + 2) % STAGES);
        else asm volatile("cp.async.commit_group;" ::: "memory");

        uint32_t aA = sb + s * STAGE_BYTES;
        uint32_t aB = aA + 2*MAT_BYTES;
#pragma unroll
        for (int kk = 0; kk < 2; kk++) {
            const uint32_t kof = kk * 32 + tig * 4;
            uint32_t ah[2][4], al[2][4];
#pragma unroll
            for (int f = 0; f < 2; f++) {
                uint32_t r0 = (uint32_t)(wm * 32 + f * 16 + g) * PITCH + kof;
                ah[f][0] = lds32(aA + r0);
                ah[f][1] = lds32(aA + r0 + 8*PITCH);
                ah[f][2] = lds32(aA + r0 + 16);
                ah[f][3] = lds32(aA + r0 + 8*PITCH + 16);
                al[f][0] = lds32(aA + MAT_BYTES + r0);
                al[f][1] = lds32(aA + MAT_BYTES + r0 + 8*PITCH);
                al[f][2] = lds32(aA + MAT_BYTES + r0 + 16);
                al[f][3] = lds32(aA + MAT_BYTES + r0 + 8*PITCH + 16);
            }
#pragma unroll
            for (int nf = 0; nf < 8; nf++) {
                uint32_t n0 = (uint32_t)(wn * 64 + nf * 8 + g) * PITCH + kof;
                uint32_t bh0 = lds32(aB + n0);
                uint32_t bh1 = lds32(aB + n0 + 16);
                uint32_t bl0 = lds32(aB + MAT_BYTES + n0);
                uint32_t bl1 = lds32(aB + MAT_BYTES + n0 + 16);
#pragma unroll
                for (int f = 0; f < 2; f++) {
                    mma16816(acc[f][nf], ah[f][0], ah[f][1], ah[f][2], ah[f][3], bh0, bh1);
                    mma16816(acc[f][nf], ah[f][0], ah[f][1], ah[f][2], ah[f][3], bl0, bl1);
                    mma16816(acc[f][nf], al[f][0], al[f][1], al[f][2], al[f][3], bh0, bh1);
                }
            }
        }
        __syncthreads();
    }

#pragma unroll
    for (int f = 0; f < 2; f++) {
        int r0 = bm + wm * 32 + f * 16 + g;
#pragma unroll
        for (int nf = 0; nf < 8; nf++) {
            int c0 = bn + wn * 64 + nf * 8 + 2 * tig;
            *(float2*)&C[(size_t)r0 * N + c0]       = make_float2(acc[f][nf][0], acc[f][nf][1]);
            *(float2*)&C[(size_t)(r0 + 8) * N + c0] = make_float2(acc[f][nf][2], acc[f][nf][3]);
        }
    }
}

// ---------------- per-graph GAT layer ----------------
// INMODE: 0 = read fp32 hpre; 1 = compute x@W1 in-kernel
// OUTMODE: 0 = fp32 out; 1 = bf16 hi/lo out
#define GAT_SMEM_WORDS (25600+400+400+3600+400+1024+8+50+400+450+450+50+50+50+2048)
#define GAT_SMEM_BYTES (GAT_SMEM_WORDS*4)

template <bool LOOPS, int INMODE, int OUTMODE>
__global__ void __launch_bounds__(512) gat_kernel(
    const float* __restrict__ xg, const float* __restrict__ W1g,
    const float* __restrict__ hpre,
    const int* __restrict__ esrc, const int* __restrict__ edst,
    const float* __restrict__ ea,
    const float* __restrict__ a_src, const float* __restrict__ a_dst,
    const float* __restrict__ We, const float* __restrict__ ae,
    const float* __restrict__ bias, float* __restrict__ xout,
    __nv_bfloat16* __restrict__ outh, __nv_bfloat16* __restrict__ outl) {
    extern __shared__ float sm[];
    float* sh_h     = sm;
    float* sh_ssrc  = sm + 25600;
    float* sh_sdst  = sh_ssrc + 400;
    float* sh_alS   = sh_sdst + 400;
    float* sh_den   = sh_alS + 3600;
    float* sh_av    = sh_den + 400;
    float* sh_weae  = sh_av + 1024;
    float* sh_easum = sh_weae + 8;
    int*   sh_amaxi = (int*)(sh_easum + 50);
    int*   sh_srcS  = sh_amaxi + 400;
    int*   sh_dstS  = sh_srcS + 450;
    int*   sh_cnt   = sh_dstS + 450;
    int*   sh_off   = sh_cnt + 50;
    int*   sh_cur   = sh_off + 50;
    float* sh_W1    = (float*)(sh_cur + 50);   // 2048

    const int g = blockIdx.x;
    const int nb = g * NODES;
    const int eb = g * EPG;
    const int tid = threadIdx.x;
    const int lane = tid & 31, wid = tid >> 5;
    const int ECNT = LOOPS ? (EPG + NODES) : EPG;

    if (tid < 400) { sh_den[tid] = 0.f; sh_amaxi[tid] = 0; }
    if (tid < NODES) { sh_cnt[tid] = 0; sh_easum[tid] = 0.f; sh_cur[tid] = 0; }
    sh_av[tid] = a_src[tid];
    sh_av[512 + tid] = a_dst[tid];
    if (INMODE == 1) {
        for (int i = tid; i < 2048; i += 512) sh_W1[i] = W1g[i];
    }
    if (tid < 8) {
        float s = 0.f;
#pragma unroll
        for (int c = 0; c < 64; c++) s += We[tid * 64 + c] * ae[tid * 64 + c];
        sh_weae[tid] = s;
    }
    __syncthreads();

    if (INMODE == 1) {
        for (int i = tid; i < NODES * FDIM; i += 512) {
            int n = i >> 9, f = i & 511;
            float4 xv = *(const float4*)(xg + (size_t)(nb + n) * 4);
            sh_h[i] = xv.x * sh_W1[f] + xv.y * sh_W1[512 + f]
                    + xv.z * sh_W1[1024 + f] + xv.w * sh_W1[1536 + f];
        }
    } else {
        const float4* s4 = (const float4*)(hpre + (size_t)nb * FDIM);
        float4* d4 = (float4*)sh_h;
        for (int i = tid; i < NODES * FDIM / 4; i += 512) d4[i] = s4[i];
    }
    for (int e = tid; e < EPG; e += 512) {
        int d = edst[eb + e] - nb;
        atomicAdd(&sh_cnt[d], 1);
        atomicAdd(&sh_easum[d], ea[eb + e]);
    }
    __syncthreads();

    for (int p = wid; p < NODES * HEADS; p += 16) {
        int n = p >> 3, h = p & 7;
        const float* hr = sh_h + n * FDIM + h * CH;
        float v0 = hr[lane], v1 = hr[lane + 32];
        float s1 = v0 * sh_av[h * CH + lane] + v1 * sh_av[h * CH + lane + 32];
        float s2 = v0 * sh_av[512 + h * CH + lane] + v1 * sh_av[512 + h * CH + lane + 32];
#pragma unroll
        for (int o = 16; o > 0; o >>= 1) {
            s1 += __shfl_xor_sync(0xffffffffu, s1, o);
            s2 += __shfl_xor_sync(0xffffffffu, s2, o);
        }
        if (lane == 0) { sh_ssrc[p] = s1; sh_sdst[p] = s2; }
    }
    __syncthreads();

    if (tid == 0) {
        int o = 0;
        for (int n = 0; n < NODES; n++) { sh_off[n] = o; o += sh_cnt[n] + (LOOPS ? 1 : 0); }
    }
    __syncthreads();

    for (int e = tid; e < ECNT; e += 512) {
        int sl, dl; float eav;
        if (e < EPG) { sl = esrc[eb + e] - nb; dl = edst[eb + e] - nb; eav = ea[eb + e]; }
        else { sl = dl = e - EPG; eav = sh_easum[dl] / fmaxf((float)sh_cnt[dl], 1.f); }
        int pos = sh_off[dl] + atomicAdd(&sh_cur[dl], 1);
        sh_srcS[pos] = sl; sh_dstS[pos] = dl;
#pragma unroll
        for (int h = 0; h < 8; h++) {
            float al = sh_ssrc[sl * 8 + h] + sh_sdst[dl * 8 + h] + eav * sh_weae[h];
            al = al > 0.f ? al : 0.2f * al;
            sh_alS[pos * 8 + h] = al;
            atomicMax(&sh_amaxi[dl * 8 + h], __float_as_int(al));
        }
    }
    __syncthreads();

    for (int i = tid; i < ECNT; i += 512) {
        int dl = sh_dstS[i];
#pragma unroll
        for (int h = 0; h < 8; h++) {
            float p = expf(sh_alS[i * 8 + h] - __int_as_float(sh_amaxi[dl * 8 + h]));
            sh_alS[i * 8 + h] = p;
            atomicAdd(&sh_den[dl * 8 + h], p);
        }
    }
    __syncthreads();
    if (tid < 400) sh_den[tid] = 1.f / (sh_den[tid] + 1e-16f);
    __syncthreads();

    const int hh = lane >> 4;
    for (int n = wid; n < NODES; n += 16) {
        float4 a0 = {0,0,0,0}, a1 = {0,0,0,0}, a2 = {0,0,0,0}, a3 = {0,0,0,0};
        float dinv[8];
#pragma unroll
        for (int h = 0; h < 8; h++) dinv[h] = sh_den[n * 8 + h];
        const int beg = sh_off[n], end = beg + sh_cur[n];
        for (int j = beg; j < end; j++) {
            const int s = sh_srcS[j];
            const float4* hs4 = (const float4*)(sh_h + s * FDIM) + lane;
            float4 u = ((const float4*)(sh_alS + j * 8))[0];
            float4 v = ((const float4*)(sh_alS + j * 8))[1];
            float p0 = u.x * dinv[0], p1 = u.y * dinv[1];
            float p2 = u.z * dinv[2], p3 = u.w * dinv[3];
            float p4 = v.x * dinv[4], p5 = v.y * dinv[5];
            float p6 = v.z * dinv[6], p7 = v.w * dinv[7];
            float q0 = hh ? p1 : p0;
            float q1 = hh ? p3 : p2;
            float q2 = hh ? p5 : p4;
            float q3 = hh ? p7 : p6;
            float4 h0 = hs4[0], h1 = hs4[32], h2 = hs4[64], h3 = hs4[96];
            a0.x += q0*h0.x; a0.y += q0*h0.y; a0.z += q0*h0.z; a0.w += q0*h0.w;
            a1.x += q1*h1.x; a1.y += q1*h1.y; a1.z += q1*h1.z; a1.w += q1*h1.w;
            a2.x += q2*h2.x; a2.y += q2*h2.y; a2.z += q2*h2.z; a2.w += q2*h2.w;
            a3.x += q3*h3.x; a3.y += q3*h3.y; a3.z += q3*h3.z; a3.w += q3*h3.w;
        }
        const float4* bp = (const float4*)bias + lane;
        float4 av[4] = {a0, a1, a2, a3};
#pragma unroll
        for (int k = 0; k < 4; k++) {
            float4 b = bp[k * 32];
            float4 v;
            v.x = fmaxf(av[k].x + b.x, 0.f);
            v.y = fmaxf(av[k].y + b.y, 0.f);
            v.z = fmaxf(av[k].z + b.z, 0.f);
            v.w = fmaxf(av[k].w + b.w, 0.f);
            if (OUTMODE == 0) {
                ((float4*)(xout + (size_t)(nb + n) * FDIM))[lane + k * 32] = v;
            } else {
                size_t fo = (size_t)(nb + n) * FDIM + lane * 4 + k * 128;
                __nv_bfloat16 h0, h1, h2, h3, l0, l1, l2, l3;
                split1(v.x, h0, l0); split1(v.y, h1, l1);
                split1(v.z, h2, l2); split1(v.w, h3, l3);
                ((__nv_bfloat162*)(outh + fo))[0] = __nv_bfloat162(h0, h1);
                ((__nv_bfloat162*)(outh + fo))[1] = __nv_bfloat162(h2, h3);
                ((__nv_bfloat162*)(outl + fo))[0] = __nv_bfloat162(l0, l1);
                ((__nv_bfloat162*)(outl + fo))[1] = __nv_bfloat162(l2, l3);
            }
        }
    }
}

// ---------------- mean pool -> graph-emb half of GRU A (hi/lo) ----------------
__global__ void pool_k(const float* __restrict__ x3, __nv_bfloat16* __restrict__ Ah,
                       __nv_bfloat16* __restrict__ Al) {
    int b = blockIdx.x;
    int f = blockIdx.y * 128 + threadIdx.x;
    float s = 0.f;
#pragma unroll 10
    for (int n = 0; n < NODES; n++) s += x3[(size_t)(b * NODES + n) * FDIM + f];
    s *= (1.f / 50.f);
    __nv_bfloat16 h, l;
    split1(s, h, l);
#pragma unroll
    for (int t = 0; t < NA; t++) {
        Ah[(size_t)(b * NA + t) * GRUI + 512 + f] = h;
        Al[(size_t)(b * NA + t) * GRUI + 512 + f] = l;
    }
}

// ---------------- agent rows -> agent half of GRU A (hi/lo) ----------------
__global__ void agent_k(const float* __restrict__ x3, __nv_bfloat16* __restrict__ Ah,
                        __nv_bfloat16* __restrict__ Al) {
    int r = blockIdx.x;           // b*5 + t
    int b = r / 5, t = r - b * 5;
    for (int f = threadIdx.x; f < 512; f += 128) {
        float v = x3[(size_t)(b * NODES + t) * FDIM + f];
        __nv_bfloat16 h, l;
        split1(v, h, l);
        Ah[(size_t)r * GRUI + f] = h;
        Al[(size_t)r * GRUI + f] = l;
    }
}

// ---------------- full GRU (5 steps in one kernel); 8 graphs per CTA ----------------
__global__ void __launch_bounds__(256) gru_all(
    const float* __restrict__ GI, const float* __restrict__ h0,
    const float* __restrict__ Whh, const float* __restrict__ bih,
    const float* __restrict__ bhh, float* __restrict__ gout,
    float* __restrict__ hlast) {
    __shared__ float sh_h[8 * GRUH];
    __shared__ float sh_gh[8 * G3];
    const int b0 = blockIdx.x * 8;
    const int tid = threadIdx.x;
    for (int i = tid; i < 8 * GRUH; i += 256) sh_h[i] = h0[b0 * GRUH + i];
    __syncthreads();
    for (int t = 0; t < NA; t++) {
#pragma unroll
        for (int v = 0; v < 12; v++) {
            int idx = v * 256 + tid;
            int gg = idx / G3, j = idx - gg * G3;
            const float* hr = sh_h + gg * GRUH;
            float acc = 0.f;
#pragma unroll 8
            for (int k = 0; k < GRUH; k++) acc += hr[k] * Whh[k * G3 + j];
            sh_gh[idx] = acc;
        }
        __syncthreads();
#pragma unroll
        for (int v = 0; v < 4; v++) {
            int idx = v * 256 + tid;
            int gg = idx >> 7, j = idx & 127;
            int bg = b0 + gg;
            const float* gi = GI + (size_t)(bg * NA + t) * G3;
            const float* gh = sh_gh + gg * G3;
            float ir = gi[j] + bih[j];
            float iz = gi[j + 128] + bih[j + 128];
            float inn = gi[j + 256] + bih[j + 256];
            float hr_ = gh[j] + bhh[j];
            float hz = gh[j + 128] + bhh[j + 128];
            float hn = gh[j + 256] + bhh[j + 256];
            float r = 1.f / (1.f + expf(-(ir + hr_)));
            float z = 1.f / (1.f + expf(-(iz + hz)));
            float nn = tanhf(inn + r * hn);
            float h = (1.f - z) * nn + z * sh_h[idx];
            sh_h[idx] = h;
            gout[(size_t)(bg * NA + t) * GRUH + j] = h;
        }
        __syncthreads();
    }
    for (int i = tid; i < 8 * GRUH; i += 256) hlast[b0 * GRUH + i] = sh_h[i];
}

// ---------------- FC head ----------------
__global__ void fc_k(const float* __restrict__ gout, const float* __restrict__ W1,
                     const float* __restrict__ b1, const float* __restrict__ W2,
                     const float* __restrict__ b2, const float* __restrict__ ls,
                     float* __restrict__ out) {
    __shared__ float g[128];
    __shared__ float f1[64];
    int r = blockIdx.x, tid = threadIdx.x;
    g[tid] = gout[(size_t)r * GRUH + tid];
    g[tid + 64] = gout[(size_t)r * GRUH + tid + 64];
    __syncthreads();
    float acc = b1[tid];
#pragma unroll 8
    for (int k = 0; k < 128; k++) acc += g[k] * W1[k * 64 + tid];
    f1[tid] = acc > 0.f ? acc : 0.f;
    __syncthreads();
    if (tid < 3) {
        float a2 = b2[tid];
#pragma unroll
        for (int k = 0; k < 64; k++) a2 += f1[k] * W2[k * 3 + tid];
        out[r * 3 + tid] = a2;
        float l = ls[tid];
        l = fminf(fmaxf(l, -20.f), 2.f);
        out[NGRAPH * NA * 3 + r * 3 + tid] = expf(l);
    }
}

// ---------------- launch ----------------
extern "C" void kernel_launch(void* const* d_in, const int* in_sizes, int n_in,
                              void* d_out, int out_size) {
    const float* x      = (const float*)d_in[0];
    const int*   ei     = (const int*)d_in[1];
    const float* ea     = (const float*)d_in[2];
    const float* hid0   = (const float*)d_in[3];
    const float* W1     = (const float*)d_in[4];
    const float* a_s1   = (const float*)d_in[5];
    const float* a_d1   = (const float*)d_in[6];
    const float* We1    = (const float*)d_in[7];
    const float* ae1    = (const float*)d_in[8];
    const float* b1     = (const float*)d_in[9];
    const float* W2     = (const float*)d_in[10];
    const float* a_s2   = (const float*)d_in[11];
    const float* a_d2   = (const float*)d_in[12];
    const float* We2    = (const float*)d_in[13];
    const float* ae2    = (const float*)d_in[14];
    const float* b2     = (const float*)d_in[15];
    const float* W3     = (const float*)d_in[16];
    const float* a_s3   = (const float*)d_in[17];
    const float* a_d3   = (const float*)d_in[18];
    const float* We3    = (const float*)d_in[19];
    const float* ae3    = (const float*)d_in[20];
    const float* b3     = (const float*)d_in[21];
    const float* Wih    = (const float*)d_in[22];
    const float* Whh    = (const float*)d_in[23];
    const float* bih    = (const float*)d_in[24];
    const float* bhh    = (const float*)d_in[25];
    const float* fc1W   = (const float*)d_in[26];
    const float* fc1b   = (const float*)d_in[27];
    const float* fc2W   = (const float*)d_in[28];
    const float* fc2b   = (const float*)d_in[29];
    const float* logstd = (const float*)d_in[30];
    float* out = (float*)d_out;

    float *bufA, *bufB, *GI, *gout;
    __nv_bfloat16 *Ah, *Al, *Bh, *Bl;
    cudaGetSymbolAddress((void**)&bufA, g_bufA);
    cudaGetSymbolAddress((void**)&bufB, g_bufB);
    cudaGetSymbolAddress((void**)&GI,   g_GI);
    cudaGetSymbolAddress((void**)&gout, g_gruout);
    cudaGetSymbolAddress((void**)&Ah, g_Ah);
    cudaGetSymbolAddress((void**)&Al, g_Al);
    cudaGetSymbolAddress((void**)&Bh, g_Bh);
    cudaGetSymbolAddress((void**)&Bl, g_Bl);

    cudaFuncSetAttribute((const void*)gat_kernel<false,1,1>,
                         cudaFuncAttributeMaxDynamicSharedMemorySize, GAT_SMEM_BYTES);
    cudaFuncSetAttribute((const void*)gat_kernel<true,0,1>,
                         cudaFuncAttributeMaxDynamicSharedMemorySize, GAT_SMEM_BYTES);
    cudaFuncSetAttribute((const void*)gat_kernel<true,0,0>,
                         cudaFuncAttributeMaxDynamicSharedMemorySize, GAT_SMEM_BYTES);
    cudaFuncSetAttribute((const void*)gemm_mma,
                         cudaFuncAttributeMaxDynamicSharedMemorySize, GEMM_SMEM);

    const int* esrc = ei;
    const int* edst = ei + NE;

    // layer 1 (fused x@W1) -> Ah/Al
    splitT_k<<<(FDIM * FDIM + 255) / 256, 256>>>(W2, Bh, Bl, FDIM, FDIM);
    gat_kernel<false,1,1><<<NGRAPH, 512, GAT_SMEM_BYTES>>>(
        x, W1, nullptr, esrc, edst, ea, a_s1, a_d1, We1, ae1, b1,
        nullptr, Ah, Al);
    // layer 2
    gemm_mma<<<dim3(FDIM / 128, NN / 128), 256, GEMM_SMEM>>>(Ah, Al, Bh, Bl, bufA,
                                                             NN, FDIM, FDIM);
    gat_kernel<true,0,1><<<NGRAPH, 512, GAT_SMEM_BYTES>>>(
        nullptr, nullptr, bufA, esrc, edst, ea, a_s2, a_d2, We2, ae2, b2,
        nullptr, Ah, Al);
    // layer 3
    splitT_k<<<(FDIM * FDIM + 255) / 256, 256>>>(W3, Bh, Bl, FDIM, FDIM);
    gemm_mma<<<dim3(FDIM / 128, NN / 128), 256, GEMM_SMEM>>>(Ah, Al, Bh, Bl, bufA,
                                                             NN, FDIM, FDIM);
    gat_kernel<true,0,0><<<NGRAPH, 512, GAT_SMEM_BYTES>>>(
        nullptr, nullptr, bufA, esrc, edst, ea, a_s3, a_d3, We3, ae3, b3,
        bufB, nullptr, nullptr);
    // pooling + agent rows -> GRU GEMM A (hi/lo), then GI GEMM
    pool_k<<<dim3(NGRAPH, FDIM / 128), 128>>>(bufB, Ah, Al);
    agent_k<<<NGRAPH * NA, 128>>>(bufB, Ah, Al);
    splitT_k<<<(GRUI * G3 + 255) / 256, 256>>>(Wih, Bh, Bl, GRUI, G3);
    gemm_mma<<<dim3(G3 / 128, (NGRAPH * NA) / 128), 256, GEMM_SMEM>>>(
        Ah, Al, Bh, Bl, GI, NGRAPH * NA, G3, GRUI);
    // GRU (all 5 steps, one kernel) — writes h_last directly into out
    gru_all<<<NGRAPH / 8, 256>>>(GI, hid0, Whh, bih, bhh, gout,
                                 out + NGRAPH * NA * 3 * 2);
    // FC head
    fc_k<<<NGRAPH * NA, 64>>>(gout, fc1W, fc1b, fc2W, fc2b, logstd, out);
}

// round 7
// speedup vs baseline: 1.0527x; 1.0527x over previous
#include <cuda_runtime.h>
#include <cuda_bf16.h>
#include <cstdint>

#define NODES 50
#define EPG   400
#define NGRAPH 512
#define NN    (NGRAPH*NODES)   // 25600
#define NE    (NGRAPH*EPG)     // 204800
#define FDIM  512
#define HEADS 8
#define CH    64
#define NA    5
#define GRUH  128
#define GRUI  1024
#define G3    384

// ---------------- scratch (static device globals; no allocation) ----------------
__device__ float g_bufA[NN*FDIM];
__device__ float g_bufB[NN*FDIM];
__device__ __nv_bfloat16 g_Ah[NN*FDIM];
__device__ __nv_bfloat16 g_Al[NN*FDIM];
__device__ __nv_bfloat16 g_Bh[GRUI*G3 > FDIM*FDIM ? GRUI*G3 : FDIM*FDIM];
__device__ __nv_bfloat16 g_Bl[GRUI*G3 > FDIM*FDIM ? GRUI*G3 : FDIM*FDIM];
__device__ float g_gemb[NGRAPH*FDIM];
__device__ float g_comb[NGRAPH*NA*GRUI];
__device__ float g_GI[NGRAPH*NA*G3];
__device__ float g_gruout[NGRAPH*NA*GRUH];

// ---------------- helpers ----------------
__device__ __forceinline__ uint32_t smem_u32(const void* p) {
    uint32_t a;
    asm("{ .reg .u64 t; cvta.to.shared.u64 t, %1; cvt.u32.u64 %0, t; }" : "=r"(a) : "l"(p));
    return a;
}
__device__ __forceinline__ void cp16(uint32_t sdst, const void* gsrc) {
    asm volatile("cp.async.cg.shared.global [%0], [%1], 16;" :: "r"(sdst), "l"(gsrc) : "memory");
}
__device__ __forceinline__ uint32_t lds32(uint32_t a) {
    uint32_t v;
    asm volatile("ld.shared.b32 %0, [%1];" : "=r"(v) : "r"(a));
    return v;
}
__device__ __forceinline__ void mma16816(float* c, uint32_t a0, uint32_t a1,
                                         uint32_t a2, uint32_t a3,
                                         uint32_t b0, uint32_t b1) {
    asm volatile(
        "mma.sync.aligned.m16n8k16.row.col.f32.bf16.bf16.f32 "
        "{%0,%1,%2,%3}, {%4,%5,%6,%7}, {%8,%9}, {%0,%1,%2,%3};"
        : "+f"(c[0]), "+f"(c[1]), "+f"(c[2]), "+f"(c[3])
        : "r"(a0), "r"(a1), "r"(a2), "r"(a3), "r"(b0), "r"(b1));
}
__device__ __forceinline__ void split1(float v, __nv_bfloat16& h, __nv_bfloat16& l) {
    h = __float2bfloat16_rn(v);
    l = __float2bfloat16_rn(v - __bfloat162float(h));
}

// ---------------- fp32 -> bf16 hi/lo split ----------------
__global__ void split_k(const float* __restrict__ in, __nv_bfloat16* __restrict__ hi,
                        __nv_bfloat16* __restrict__ lo, int n4) {
    int i = blockIdx.x * 256 + threadIdx.x;
    if (i >= n4) return;
    float4 v = ((const float4*)in)[i];
    __nv_bfloat16 h0, h1, h2, h3, l0, l1, l2, l3;
    split1(v.x, h0, l0); split1(v.y, h1, l1);
    split1(v.z, h2, l2); split1(v.w, h3, l3);
    ((__nv_bfloat162*)hi)[i*2]   = __nv_bfloat162(h0, h1);
    ((__nv_bfloat162*)hi)[i*2+1] = __nv_bfloat162(h2, h3);
    ((__nv_bfloat162*)lo)[i*2]   = __nv_bfloat162(l0, l1);
    ((__nv_bfloat162*)lo)[i*2+1] = __nv_bfloat162(l2, l3);
}

// W [K,N] fp32 -> Wt [N,K] bf16 hi/lo (transposed)
__global__ void splitT_k(const float* __restrict__ W, __nv_bfloat16* __restrict__ hi,
                         __nv_bfloat16* __restrict__ lo, int K, int N) {
    int idx = blockIdx.x * 256 + threadIdx.x;
    if (idx >= N * K) return;
    int n = idx / K, k = idx - n * K;
    float v = W[(size_t)k * N + n];
    __nv_bfloat16 h, l;
    split1(v, h, l);
    hi[idx] = h;
    lo[idx] = l;
}

// ---------------- HMMA bf16-split GEMM: C[M,N] = A[M,K] * B[N,K]^T ----------------
#define STAGES 3
#define PITCH 80
#define MAT_BYTES (128*PITCH)
#define STAGE_BYTES (4*MAT_BYTES)
#define GEMM_SMEM (STAGES*STAGE_BYTES)

__global__ void __launch_bounds__(256) gemm_mma(
    const __nv_bfloat16* __restrict__ Ah, const __nv_bfloat16* __restrict__ Al,
    const __nv_bfloat16* __restrict__ Bh, const __nv_bfloat16* __restrict__ Bl,
    float* __restrict__ C, int M, int N, int K) {
    extern __shared__ char sm8[];
    const uint32_t sb = smem_u32(sm8);
    const int tid = threadIdx.x;
    const int lane = tid & 31, wid = tid >> 5;
    const int wm = wid & 3, wn = wid >> 2;
    const int bm = blockIdx.y * 128, bn = blockIdx.x * 128;
    const int g = lane >> 2, tig = lane & 3;
    const int NCH = K >> 5;

    const char* pAh = (const char*)Ah;
    const char* pAl = (const char*)Al;
    const char* pBh = (const char*)Bh;
    const char* pBl = (const char*)Bl;
    const size_t rowb = (size_t)K * 2;

    auto load_stage = [&](int kc, int s) {
        uint32_t sbase = sb + s * STAGE_BYTES;
        size_t kb = (size_t)kc * 64;
#pragma unroll
        for (int i = tid; i < 512; i += 256) {
            int r = i >> 2, gg = i & 3;
            uint32_t so = sbase + r * PITCH + gg * 16;
            size_t ga = (size_t)(bm + r) * rowb + kb + gg * 16;
            size_t gb = (size_t)(bn + r) * rowb + kb + gg * 16;
            cp16(so,                 pAh + ga);
            cp16(so + MAT_BYTES,     pAl + ga);
            cp16(so + 2*MAT_BYTES,   pBh + gb);
            cp16(so + 3*MAT_BYTES,   pBl + gb);
        }
        asm volatile("cp.async.commit_group;" ::: "memory");
    };

    float acc[2][8][4];
#pragma unroll
    for (int f = 0; f < 2; f++)
#pragma unroll
        for (int nf = 0; nf < 8; nf++)
#pragma unroll
            for (int c = 0; c < 4; c++) acc[f][nf][c] = 0.f;

    load_stage(0, 0);
    load_stage(1, 1);

    for (int kc = 0; kc < NCH; kc++) {
        int s = kc % STAGES;
        asm volatile("cp.async.wait_group 1;" ::: "memory");
        __syncthreads();
        if (kc + 2 < NCH) load_stage(kc + 2, (kc + 2) % STAGES);
        else asm volatile("cp.async.commit_group;" ::: "memory");

        uint32_t aA = sb + s * STAGE_BYTES;
        uint32_t aB = aA + 2*MAT_BYTES;
#pragma unroll
        for (int kk = 0; kk < 2; kk++) {
            const uint32_t kof = kk * 32 + tig * 4;
            uint32_t ah[2][4], al[2][4];
#pragma unroll
            for (int f = 0; f < 2; f++) {
                uint32_t r0 = (uint32_t)(wm * 32 + f * 16 + g) * PITCH + kof;
                ah[f][0] = lds32(aA + r0);
                ah[f][1] = lds32(aA + r0 + 8*PITCH);
                ah[f][2] = lds32(aA + r0 + 16);
                ah[f][3] = lds32(aA + r0 + 8*PITCH + 16);
                al[f][0] = lds32(aA + MAT_BYTES + r0);
                al[f][1] = lds32(aA + MAT_BYTES + r0 + 8*PITCH);
                al[f][2] = lds32(aA + MAT_BYTES + r0 + 16);
                al[f][3] = lds32(aA + MAT_BYTES + r0 + 8*PITCH + 16);
            }
#pragma unroll
            for (int nf = 0; nf < 8; nf++) {
                uint32_t n0 = (uint32_t)(wn * 64 + nf * 8 + g) * PITCH + kof;
                uint32_t bh0 = lds32(aB + n0);
                uint32_t bh1 = lds32(aB + n0 + 16);
                uint32_t bl0 = lds32(aB + MAT_BYTES + n0);
                uint32_t bl1 = lds32(aB + MAT_BYTES + n0 + 16);
#pragma unroll
                for (int f = 0; f < 2; f++) {
                    mma16816(acc[f][nf], ah[f][0], ah[f][1], ah[f][2], ah[f][3], bh0, bh1);
                    mma16816(acc[f][nf], ah[f][0], ah[f][1], ah[f][2], ah[f][3], bl0, bl1);
                    mma16816(acc[f][nf], al[f][0], al[f][1], al[f][2], al[f][3], bh0, bh1);
                }
            }
        }
        __syncthreads();
    }

#pragma unroll
    for (int f = 0; f < 2; f++) {
        int r0 = bm + wm * 32 + f * 16 + g;
#pragma unroll
        for (int nf = 0; nf < 8; nf++) {
            int c0 = bn + wn * 64 + nf * 8 + 2 * tig;
            *(float2*)&C[(size_t)r0 * N + c0]       = make_float2(acc[f][nf][0], acc[f][nf][1]);
            *(float2*)&C[(size_t)(r0 + 8) * N + c0] = make_float2(acc[f][nf][2], acc[f][nf][3]);
        }
    }
}

// ---------------- x @ W1  (K=4) ----------------
__global__ void lin1_k(const float* __restrict__ x, const float* __restrict__ W,
                       float* __restrict__ out) {
    int idx = blockIdx.x * 256 + threadIdx.x;
    int n = idx >> 9, f = idx & 511;
    const float* xr = x + n * 4;
    out[idx] = xr[0]*W[f] + xr[1]*W[512+f] + xr[2]*W[1024+f] + xr[3]*W[1536+f];
}

// ---------------- per-graph GAT layer v2 (no smem h; 256 threads; high occupancy) --
template <bool LOOPS>
__global__ void __launch_bounds__(256, 4) gat_kernel(
    const float* __restrict__ hpre,
    const int* __restrict__ esrc, const int* __restrict__ edst,
    const float* __restrict__ ea,
    const float* __restrict__ a_src, const float* __restrict__ a_dst,
    const float* __restrict__ We, const float* __restrict__ ae,
    const float* __restrict__ bias, float* __restrict__ xout) {
    __shared__ float sh_ssrc[400];
    __shared__ float sh_sdst[400];
    __shared__ float sh_alS[3600];
    __shared__ float sh_den[400];
    __shared__ float sh_av[1024];
    __shared__ float sh_weae[8];
    __shared__ float sh_easum[52];
    __shared__ int   sh_amaxi[400];
    __shared__ int   sh_srcS[452];
    __shared__ int   sh_dstS[452];
    __shared__ int   sh_cnt[52];
    __shared__ int   sh_off[52];
    __shared__ int   sh_cur[52];

    const int g = blockIdx.x;
    const int nb = g * NODES;
    const int eb = g * EPG;
    const int tid = threadIdx.x;
    const int lane = tid & 31, wid = tid >> 5;
    const int ECNT = LOOPS ? (EPG + NODES) : EPG;

    // init
    for (int i = tid; i < 400; i += 256) { sh_den[i] = 0.f; sh_amaxi[i] = 0; }
    if (tid < NODES) { sh_cnt[tid] = 0; sh_easum[tid] = 0.f; sh_cur[tid] = 0; }
    for (int i = tid; i < 512; i += 256) {
        sh_av[i] = a_src[i];
        sh_av[512 + i] = a_dst[i];
    }
    if (tid < 8) {
        float s = 0.f;
#pragma unroll
        for (int c = 0; c < 64; c++) s += We[tid * 64 + c] * ae[tid * 64 + c];
        sh_weae[tid] = s;
    }
    __syncthreads();

    // count incoming edges + edge-attr sums
    for (int e = tid; e < EPG; e += 256) {
        int d = edst[eb + e] - nb;
        atomicAdd(&sh_cnt[d], 1);
        atomicAdd(&sh_easum[d], ea[eb + e]);
    }
    __syncthreads();

    // phase 1: per-(node,head) attention scores — warp per node, global h reads
    for (int n = wid; n < NODES; n += 8) {
        const float4* hr = (const float4*)(hpre + (size_t)(nb + n) * FDIM);
#pragma unroll
        for (int k = 0; k < 4; k++) {
            float4 v = hr[lane + 32 * k];
            int f = 4 * lane + 128 * k;
            float4 as = *(const float4*)(sh_av + f);
            float4 ad = *(const float4*)(sh_av + 512 + f);
            float s1 = v.x*as.x + v.y*as.y + v.z*as.z + v.w*as.w;
            float s2 = v.x*ad.x + v.y*ad.y + v.z*ad.z + v.w*ad.w;
#pragma unroll
            for (int o = 8; o > 0; o >>= 1) {
                s1 += __shfl_xor_sync(0xffffffffu, s1, o);
                s2 += __shfl_xor_sync(0xffffffffu, s2, o);
            }
            if ((lane & 15) == 0) {
                int head = 2 * k + (lane >> 4);
                sh_ssrc[n * 8 + head] = s1;
                sh_sdst[n * 8 + head] = s2;
            }
        }
    }
    __syncthreads();

    // phase 2: exclusive scan of per-dst counts
    if (tid == 0) {
        int o = 0;
        for (int n = 0; n < NODES; n++) { sh_off[n] = o; o += sh_cnt[n] + (LOOPS ? 1 : 0); }
    }
    __syncthreads();

    // phase 3: logits (leaky-relu) in dst-sorted order + per-dst max
    for (int e = tid; e < ECNT; e += 256) {
        int sl, dl; float eav;
        if (e < EPG) { sl = esrc[eb + e] - nb; dl = edst[eb + e] - nb; eav = ea[eb + e]; }
        else { sl = dl = e - EPG; eav = sh_easum[dl] / fmaxf((float)sh_cnt[dl], 1.f); }
        int pos = sh_off[dl] + atomicAdd(&sh_cur[dl], 1);
        sh_srcS[pos] = sl; sh_dstS[pos] = dl;
#pragma unroll
        for (int h = 0; h < 8; h++) {
            float al = sh_ssrc[sl * 8 + h] + sh_sdst[dl * 8 + h] + eav * sh_weae[h];
            al = al > 0.f ? al : 0.2f * al;
            sh_alS[pos * 8 + h] = al;
            atomicMax(&sh_amaxi[dl * 8 + h], __float_as_int(al));
        }
    }
    __syncthreads();

    // phase 4: exp + denom
    for (int i = tid; i < ECNT; i += 256) {
        int dl = sh_dstS[i];
#pragma unroll
        for (int h = 0; h < 8; h++) {
            float p = __expf(sh_alS[i * 8 + h] - __int_as_float(sh_amaxi[dl * 8 + h]));
            sh_alS[i * 8 + h] = p;
            atomicAdd(&sh_den[dl * 8 + h], p);
        }
    }
    __syncthreads();
    for (int i = tid; i < 400; i += 256) sh_den[i] = 1.f / (sh_den[i] + 1e-16f);
    __syncthreads();

    // phase 5: aggregation — warp per node, global h reads (L1/L2-cached)
    const int hh = lane >> 4;
    for (int n = wid; n < NODES; n += 8) {
        float4 a0 = {0,0,0,0}, a1 = {0,0,0,0}, a2 = {0,0,0,0}, a3 = {0,0,0,0};
        float dinv[8];
#pragma unroll
        for (int h = 0; h < 8; h++) dinv[h] = sh_den[n * 8 + h];
        const int beg = sh_off[n], end = beg + sh_cur[n];
        for (int j = beg; j < end; j++) {
            const int s = sh_srcS[j];
            const float4* hs4 = (const float4*)(hpre + (size_t)(nb + s) * FDIM) + lane;
            float4 u = ((const float4*)(sh_alS + j * 8))[0];
            float4 v = ((const float4*)(sh_alS + j * 8))[1];
            float p0 = u.x * dinv[0], p1 = u.y * dinv[1];
            float p2 = u.z * dinv[2], p3 = u.w * dinv[3];
            float p4 = v.x * dinv[4], p5 = v.y * dinv[5];
            float p6 = v.z * dinv[6], p7 = v.w * dinv[7];
            float q0 = hh ? p1 : p0;
            float q1 = hh ? p3 : p2;
            float q2 = hh ? p5 : p4;
            float q3 = hh ? p7 : p6;
            float4 h0 = hs4[0], h1 = hs4[32], h2 = hs4[64], h3 = hs4[96];
            a0.x += q0*h0.x; a0.y += q0*h0.y; a0.z += q0*h0.z; a0.w += q0*h0.w;
            a1.x += q1*h1.x; a1.y += q1*h1.y; a1.z += q1*h1.z; a1.w += q1*h1.w;
            a2.x += q2*h2.x; a2.y += q2*h2.y; a2.z += q2*h2.z; a2.w += q2*h2.w;
            a3.x += q3*h3.x; a3.y += q3*h3.y; a3.z += q3*h3.z; a3.w += q3*h3.w;
        }
        float4* op = (float4*)(xout + (size_t)(nb + n) * FDIM) + lane;
        const float4* bp = (const float4*)bias + lane;
        float4 b;
        b = bp[0];
        a0.x = fmaxf(a0.x + b.x, 0.f); a0.y = fmaxf(a0.y + b.y, 0.f);
        a0.z = fmaxf(a0.z + b.z, 0.f); a0.w = fmaxf(a0.w + b.w, 0.f); op[0] = a0;
        b = bp[32];
        a1.x = fmaxf(a1.x + b.x, 0.f); a1.y = fmaxf(a1.y + b.y, 0.f);
        a1.z = fmaxf(a1.z + b.z, 0.f); a1.w = fmaxf(a1.w + b.w, 0.f); op[32] = a1;
        b = bp[64];
        a2.x = fmaxf(a2.x + b.x, 0.f); a2.y = fmaxf(a2.y + b.y, 0.f);
        a2.z = fmaxf(a2.z + b.z, 0.f); a2.w = fmaxf(a2.w + b.w, 0.f); op[64] = a2;
        b = bp[96];
        a3.x = fmaxf(a3.x + b.x, 0.f); a3.y = fmaxf(a3.y + b.y, 0.f);
        a3.z = fmaxf(a3.z + b.z, 0.f); a3.w = fmaxf(a3.w + b.w, 0.f); op[96] = a3;
    }
}

// ---------------- mean pool ----------------
__global__ void pool_k(const float* __restrict__ x3, float* __restrict__ gemb) {
    int b = blockIdx.x;
    int f = blockIdx.y * 128 + threadIdx.x;
    float s = 0.f;
#pragma unroll 10
    for (int n = 0; n < NODES; n++) s += x3[(size_t)(b * NODES + n) * FDIM + f];
    gemb[b * FDIM + f] = s * (1.f / 50.f);
}

// ---------------- build combined ----------------
__global__ void gather_k(const float* __restrict__ x3, const float* __restrict__ gemb,
                         float* __restrict__ comb) {
    int r = blockIdx.x;
    int b = r / 5, t = r - b * 5;
    for (int i = threadIdx.x; i < GRUI; i += 256)
        comb[(size_t)r * GRUI + i] =
            (i < 512) ? x3[(size_t)(b * NODES + t) * FDIM + i] : gemb[b * FDIM + i - 512];
}

// ---------------- full GRU (5 steps in one kernel); 8 graphs per CTA ----------------
__global__ void __launch_bounds__(256) gru_all(
    const float* __restrict__ GI, const float* __restrict__ h0,
    const float* __restrict__ Whh, const float* __restrict__ bih,
    const float* __restrict__ bhh, float* __restrict__ gout,
    float* __restrict__ hlast) {
    __shared__ float sh_h[8 * GRUH];
    __shared__ float sh_gh[8 * G3];
    const int b0 = blockIdx.x * 8;
    const int tid = threadIdx.x;
    for (int i = tid; i < 8 * GRUH; i += 256) sh_h[i] = h0[b0 * GRUH + i];
    __syncthreads();
    for (int t = 0; t < NA; t++) {
#pragma unroll
        for (int v = 0; v < 12; v++) {
            int idx = v * 256 + tid;
            int gg = idx / G3, j = idx - gg * G3;
            const float* hr = sh_h + gg * GRUH;
            float acc = 0.f;
#pragma unroll 8
            for (int k = 0; k < GRUH; k++) acc += hr[k] * Whh[k * G3 + j];
            sh_gh[idx] = acc;
        }
        __syncthreads();
#pragma unroll
        for (int v = 0; v < 4; v++) {
            int idx = v * 256 + tid;
            int gg = idx >> 7, j = idx & 127;
            int bg = b0 + gg;
            const float* gi = GI + (size_t)(bg * NA + t) * G3;
            const float* gh = sh_gh + gg * G3;
            float ir = gi[j] + bih[j];
            float iz = gi[j + 128] + bih[j + 128];
            float inn = gi[j + 256] + bih[j + 256];
            float hr_ = gh[j] + bhh[j];
            float hz = gh[j + 128] + bhh[j + 128];
            float hn = gh[j + 256] + bhh[j + 256];
            float r = 1.f / (1.f + expf(-(ir + hr_)));
            float z = 1.f / (1.f + expf(-(iz + hz)));
            float nn = tanhf(inn + r * hn);
            float h = (1.f - z) * nn + z * sh_h[idx];
            sh_h[idx] = h;
            gout[(size_t)(bg * NA + t) * GRUH + j] = h;
        }
        __syncthreads();
    }
    for (int i = tid; i < 8 * GRUH; i += 256) hlast[b0 * GRUH + i] = sh_h[i];
}

// ---------------- FC head ----------------
__global__ void fc_k(const float* __restrict__ gout, const float* __restrict__ W1,
                     const float* __restrict__ b1, const float* __restrict__ W2,
                     const float* __restrict__ b2, const float* __restrict__ ls,
                     float* __restrict__ out) {
    __shared__ float g[128];
    __shared__ float f1[64];
    int r = blockIdx.x, tid = threadIdx.x;
    g[tid] = gout[(size_t)r * GRUH + tid];
    g[tid + 64] = gout[(size_t)r * GRUH + tid + 64];
    __syncthreads();
    float acc = b1[tid];
#pragma unroll 8
    for (int k = 0; k < 128; k++) acc += g[k] * W1[k * 64 + tid];
    f1[tid] = acc > 0.f ? acc : 0.f;
    __syncthreads();
    if (tid < 3) {
        float a2 = b2[tid];
#pragma unroll
        for (int k = 0; k < 64; k++) a2 += f1[k] * W2[k * 3 + tid];
        out[r * 3 + tid] = a2;
        float l = ls[tid];
        l = fminf(fmaxf(l, -20.f), 2.f);
        out[NGRAPH * NA * 3 + r * 3 + tid] = expf(l);
    }
}

// ---------------- launch ----------------
extern "C" void kernel_launch(void* const* d_in, const int* in_sizes, int n_in,
                              void* d_out, int out_size) {
    const float* x      = (const float*)d_in[0];
    const int*   ei     = (const int*)d_in[1];
    const float* ea     = (const float*)d_in[2];
    const float* hid0   = (const float*)d_in[3];
    const float* W1     = (const float*)d_in[4];
    const float* a_s1   = (const float*)d_in[5];
    const float* a_d1   = (const float*)d_in[6];
    const float* We1    = (const float*)d_in[7];
    const float* ae1    = (const float*)d_in[8];
    const float* b1     = (const float*)d_in[9];
    const float* W2     = (const float*)d_in[10];
    const float* a_s2   = (const float*)d_in[11];
    const float* a_d2   = (const float*)d_in[12];
    const float* We2    = (const float*)d_in[13];
    const float* ae2    = (const float*)d_in[14];
    const float* b2     = (const float*)d_in[15];
    const float* W3     = (const float*)d_in[16];
    const float* a_s3   = (const float*)d_in[17];
    const float* a_d3   = (const float*)d_in[18];
    const float* We3    = (const float*)d_in[19];
    const float* ae3    = (const float*)d_in[20];
    const float* b3     = (const float*)d_in[21];
    const float* Wih    = (const float*)d_in[22];
    const float* Whh    = (const float*)d_in[23];
    const float* bih    = (const float*)d_in[24];
    const float* bhh    = (const float*)d_in[25];
    const float* fc1W   = (const float*)d_in[26];
    const float* fc1b   = (const float*)d_in[27];
    const float* fc2W   = (const float*)d_in[28];
    const float* fc2b   = (const float*)d_in[29];
    const float* logstd = (const float*)d_in[30];
    float* out = (float*)d_out;

    float *bufA, *bufB, *gemb, *comb, *GI, *gout;
    __nv_bfloat16 *Ah, *Al, *Bh, *Bl;
    cudaGetSymbolAddress((void**)&bufA, g_bufA);
    cudaGetSymbolAddress((void**)&bufB, g_bufB);
    cudaGetSymbolAddress((void**)&gemb, g_gemb);
    cudaGetSymbolAddress((void**)&comb, g_comb);
    cudaGetSymbolAddress((void**)&GI,   g_GI);
    cudaGetSymbolAddress((void**)&gout, g_gruout);
    cudaGetSymbolAddress((void**)&Ah, g_Ah);
    cudaGetSymbolAddress((void**)&Al, g_Al);
    cudaGetSymbolAddress((void**)&Bh, g_Bh);
    cudaGetSymbolAddress((void**)&Bl, g_Bl);

    cudaFuncSetAttribute((const void*)gemm_mma,
                         cudaFuncAttributeMaxDynamicSharedMemorySize, GEMM_SMEM);

    const int* esrc = ei;
    const int* edst = ei + NE;

    // layer 1
    lin1_k<<<(NN * FDIM) / 256, 256>>>(x, W1, bufA);
    gat_kernel<false><<<NGRAPH, 256>>>(bufA, esrc, edst, ea,
                                       a_s1, a_d1, We1, ae1, b1, bufB);
    // layer 2
    splitT_k<<<(FDIM * FDIM + 255) / 256, 256>>>(W2, Bh, Bl, FDIM, FDIM);
    split_k<<<(NN * FDIM / 4 + 255) / 256, 256>>>(bufB, Ah, Al, NN * FDIM / 4);
    gemm_mma<<<dim3(FDIM / 128, NN / 128), 256, GEMM_SMEM>>>(Ah, Al, Bh, Bl, bufA,
                                                             NN, FDIM, FDIM);
    gat_kernel<true><<<NGRAPH, 256>>>(bufA, esrc, edst, ea,
                                      a_s2, a_d2, We2, ae2, b2, bufB);
    // layer 3
    splitT_k<<<(FDIM * FDIM + 255) / 256, 256>>>(W3, Bh, Bl, FDIM, FDIM);
    split_k<<<(NN * FDIM / 4 + 255) / 256, 256>>>(bufB, Ah, Al, NN * FDIM / 4);
    gemm_mma<<<dim3(FDIM / 128, NN / 128), 256, GEMM_SMEM>>>(Ah, Al, Bh, Bl, bufA,
                                                             NN, FDIM, FDIM);
    gat_kernel<true><<<NGRAPH, 256>>>(bufA, esrc, edst, ea,
                                      a_s3, a_d3, We3, ae3, b3, bufB);
    // pooling + GRU input GEMM
    pool_k<<<dim3(NGRAPH, FDIM / 128), 128>>>(bufB, gemb);
    gather_k<<<NGRAPH * NA, 256>>>(bufB, gemb, comb);
    splitT_k<<<(GRUI * G3 + 255) / 256, 256>>>(Wih, Bh, Bl, GRUI, G3);
    split_k<<<(NGRAPH * NA * GRUI / 4 + 255) / 256, 256>>>(comb, Ah, Al,
                                                           NGRAPH * NA * GRUI / 4);
    gemm_mma<<<dim3(G3 / 128, (NGRAPH * NA) / 128), 256, GEMM_SMEM>>>(
        Ah, Al, Bh, Bl, GI, NGRAPH * NA, G3, GRUI);
    // GRU (single kernel; reads hid0 directly, writes h_last into out)
    gru_all<<<NGRAPH / 8, 256>>>(GI, hid0, Whh, bih, bhh, gout,
                                 out + NGRAPH * NA * 3 * 2);
    // FC head
    fc_k<<<NGRAPH * NA, 64>>>(gout, fc1W, fc1b, fc2W, fc2b, logstd, out);
}

// round 8
// speedup vs baseline: 1.3099x; 1.2444x over previous
#include <cuda_runtime.h>
#include <cuda_bf16.h>
#include <cstdint>

#define NODES 50
#define EPG   400
#define NGRAPH 512
#define NN    (NGRAPH*NODES)   // 25600
#define NE    (NGRAPH*EPG)     // 204800
#define FDIM  512
#define HEADS 8
#define CH    64
#define NA    5
#define GRUH  128
#define GRUI  1024
#define G3    384
#define EMAX  456              // padded per-graph edge capacity (450 used)

// ---------------- scratch (static device globals; no allocation) ----------------
__device__ float g_bufA[NN*FDIM];
__device__ float g_bufB[NN*FDIM];
__device__ __nv_bfloat16 g_Ah[NN*FDIM];
__device__ __nv_bfloat16 g_Al[NN*FDIM];
__device__ __nv_bfloat16 g_Bh[GRUI*G3 > FDIM*FDIM ? GRUI*G3 : FDIM*FDIM];
__device__ __nv_bfloat16 g_Bl[GRUI*G3 > FDIM*FDIM ? GRUI*G3 : FDIM*FDIM];
__device__ float g_alpha[NGRAPH*EMAX*HEADS];
__device__ int   g_srcb[NGRAPH*EMAX];
__device__ int   g_offb[NGRAPH*51];
__device__ float g_gemb[NGRAPH*FDIM];
__device__ float g_comb[NGRAPH*NA*GRUI];
__device__ float g_GI[NGRAPH*NA*G3];
__device__ float g_GHbuf[NGRAPH*G3];
__device__ float g_h0[NGRAPH*GRUH];
__device__ float g_h1[NGRAPH*GRUH];
__device__ float g_gruout[NGRAPH*NA*GRUH];

// ---------------- helpers ----------------
__device__ __forceinline__ uint32_t smem_u32(const void* p) {
    uint32_t a;
    asm("{ .reg .u64 t; cvta.to.shared.u64 t, %1; cvt.u32.u64 %0, t; }" : "=r"(a) : "l"(p));
    return a;
}
__device__ __forceinline__ void cp16(uint32_t sdst, const void* gsrc) {
    asm volatile("cp.async.cg.shared.global [%0], [%1], 16;" :: "r"(sdst), "l"(gsrc) : "memory");
}
__device__ __forceinline__ uint32_t lds32(uint32_t a) {
    uint32_t v;
    asm volatile("ld.shared.b32 %0, [%1];" : "=r"(v) : "r"(a));
    return v;
}
__device__ __forceinline__ void mma16816(float* c, uint32_t a0, uint32_t a1,
                                         uint32_t a2, uint32_t a3,
                                         uint32_t b0, uint32_t b1) {
    asm volatile(
        "mma.sync.aligned.m16n8k16.row.col.f32.bf16.bf16.f32 "
        "{%0,%1,%2,%3}, {%4,%5,%6,%7}, {%8,%9}, {%0,%1,%2,%3};"
        : "+f"(c[0]), "+f"(c[1]), "+f"(c[2]), "+f"(c[3])
        : "r"(a0), "r"(a1), "r"(a2), "r"(a3), "r"(b0), "r"(b1));
}
__device__ __forceinline__ void split1(float v, __nv_bfloat16& h, __nv_bfloat16& l) {
    h = __float2bfloat16_rn(v);
    l = __float2bfloat16_rn(v - __bfloat162float(h));
}

// ---------------- fp32 -> bf16 hi/lo split ----------------
__global__ void split_k(const float* __restrict__ in, __nv_bfloat16* __restrict__ hi,
                        __nv_bfloat16* __restrict__ lo, int n4) {
    int i = blockIdx.x * 256 + threadIdx.x;
    if (i >= n4) return;
    float4 v = ((const float4*)in)[i];
    __nv_bfloat16 h0, h1, h2, h3, l0, l1, l2, l3;
    split1(v.x, h0, l0); split1(v.y, h1, l1);
    split1(v.z, h2, l2); split1(v.w, h3, l3);
    ((__nv_bfloat162*)hi)[i*2]   = __nv_bfloat162(h0, h1);
    ((__nv_bfloat162*)hi)[i*2+1] = __nv_bfloat162(h2, h3);
    ((__nv_bfloat162*)lo)[i*2]   = __nv_bfloat162(l0, l1);
    ((__nv_bfloat162*)lo)[i*2+1] = __nv_bfloat162(l2, l3);
}

// W [K,N] fp32 -> Wt [N,K] bf16 hi/lo (transposed)
__global__ void splitT_k(const float* __restrict__ W, __nv_bfloat16* __restrict__ hi,
                         __nv_bfloat16* __restrict__ lo, int K, int N) {
    int idx = blockIdx.x * 256 + threadIdx.x;
    if (idx >= N * K) return;
    int n = idx / K, k = idx - n * K;
    float v = W[(size_t)k * N + n];
    __nv_bfloat16 h, l;
    split1(v, h, l);
    hi[idx] = h;
    lo[idx] = l;
}

// ---------------- HMMA bf16-split GEMM: C[M,N] = A[M,K] * B[N,K]^T ----------------
#define STAGES 3
#define PITCH 80
#define MAT_BYTES (128*PITCH)
#define STAGE_BYTES (4*MAT_BYTES)
#define GEMM_SMEM (STAGES*STAGE_BYTES)

__global__ void __launch_bounds__(256) gemm_mma(
    const __nv_bfloat16* __restrict__ Ah, const __nv_bfloat16* __restrict__ Al,
    const __nv_bfloat16* __restrict__ Bh, const __nv_bfloat16* __restrict__ Bl,
    float* __restrict__ C, int M, int N, int K) {
    extern __shared__ char sm8[];
    const uint32_t sb = smem_u32(sm8);
    const int tid = threadIdx.x;
    const int lane = tid & 31, wid = tid >> 5;
    const int wm = wid & 3, wn = wid >> 2;
    const int bm = blockIdx.y * 128, bn = blockIdx.x * 128;
    const int g = lane >> 2, tig = lane & 3;
    const int NCH = K >> 5;

    const char* pAh = (const char*)Ah;
    const char* pAl = (const char*)Al;
    const char* pBh = (const char*)Bh;
    const char* pBl = (const char*)Bl;
    const size_t rowb = (size_t)K * 2;

    auto load_stage = [&](int kc, int s) {
        uint32_t sbase = sb + s * STAGE_BYTES;
        size_t kb = (size_t)kc * 64;
#pragma unroll
        for (int i = tid; i < 512; i += 256) {
            int r = i >> 2, gg = i & 3;
            uint32_t so = sbase + r * PITCH + gg * 16;
            size_t ga = (size_t)(bm + r) * rowb + kb + gg * 16;
            size_t gb = (size_t)(bn + r) * rowb + kb + gg * 16;
            cp16(so,                 pAh + ga);
            cp16(so + MAT_BYTES,     pAl + ga);
            cp16(so + 2*MAT_BYTES,   pBh + gb);
            cp16(so + 3*MAT_BYTES,   pBl + gb);
        }
        asm volatile("cp.async.commit_group;" ::: "memory");
    };

    float acc[2][8][4];
#pragma unroll
    for (int f = 0; f < 2; f++)
#pragma unroll
        for (int nf = 0; nf < 8; nf++)
#pragma unroll
            for (int c = 0; c < 4; c++) acc[f][nf][c] = 0.f;

    load_stage(0, 0);
    load_stage(1, 1);

    for (int kc = 0; kc < NCH; kc++) {
        int s = kc % STAGES;
        asm volatile("cp.async.wait_group 1;" ::: "memory");
        __syncthreads();
        if (kc + 2 < NCH) load_stage(kc + 2, (kc + 2) % STAGES);
        else asm volatile("cp.async.commit_group;" ::: "memory");

        uint32_t aA = sb + s * STAGE_BYTES;
        uint32_t aB = aA + 2*MAT_BYTES;
#pragma unroll
        for (int kk = 0; kk < 2; kk++) {
            const uint32_t kof = kk * 32 + tig * 4;
            uint32_t ah[2][4], al[2][4];
#pragma unroll
            for (int f = 0; f < 2; f++) {
                uint32_t r0 = (uint32_t)(wm * 32 + f * 16 + g) * PITCH + kof;
                ah[f][0] = lds32(aA + r0);
                ah[f][1] = lds32(aA + r0 + 8*PITCH);
                ah[f][2] = lds32(aA + r0 + 16);
                ah[f][3] = lds32(aA + r0 + 8*PITCH + 16);
                al[f][0] = lds32(aA + MAT_BYTES + r0);
                al[f][1] = lds32(aA + MAT_BYTES + r0 + 8*PITCH);
                al[f][2] = lds32(aA + MAT_BYTES + r0 + 16);
                al[f][3] = lds32(aA + MAT_BYTES + r0 + 8*PITCH + 16);
            }
#pragma unroll
            for (int nf = 0; nf < 8; nf++) {
                uint32_t n0 = (uint32_t)(wn * 64 + nf * 8 + g) * PITCH + kof;
                uint32_t bh0 = lds32(aB + n0);
                uint32_t bh1 = lds32(aB + n0 + 16);
                uint32_t bl0 = lds32(aB + MAT_BYTES + n0);
                uint32_t bl1 = lds32(aB + MAT_BYTES + n0 + 16);
#pragma unroll
                for (int f = 0; f < 2; f++) {
                    mma16816(acc[f][nf], ah[f][0], ah[f][1], ah[f][2], ah[f][3], bh0, bh1);
                    mma16816(acc[f][nf], ah[f][0], ah[f][1], ah[f][2], ah[f][3], bl0, bl1);
                    mma16816(acc[f][nf], al[f][0], al[f][1], al[f][2], al[f][3], bh0, bh1);
                }
            }
        }
        __syncthreads();
    }

#pragma unroll
    for (int f = 0; f < 2; f++) {
        int r0 = bm + wm * 32 + f * 16 + g;
#pragma unroll
        for (int nf = 0; nf < 8; nf++) {
            int c0 = bn + wn * 64 + nf * 8 + 2 * tig;
            *(float2*)&C[(size_t)r0 * N + c0]       = make_float2(acc[f][nf][0], acc[f][nf][1]);
            *(float2*)&C[(size_t)(r0 + 8) * N + c0] = make_float2(acc[f][nf][2], acc[f][nf][3]);
        }
    }
}

// ---------------- x @ W1  (K=4) ----------------
__global__ void lin1_k(const float* __restrict__ x, const float* __restrict__ W,
                       float* __restrict__ out) {
    int idx = blockIdx.x * 256 + threadIdx.x;
    int n = idx >> 9, f = idx & 511;
    const float* xr = x + n * 4;
    out[idx] = xr[0]*W[f] + xr[1]*W[512+f] + xr[2]*W[1024+f] + xr[3]*W[1536+f];
}

// ---------------- GAT kernel A: attention (per graph, small smem, hi occ) --------
template <bool LOOPS>
__global__ void __launch_bounds__(256) gat_attn(
    const float* __restrict__ hpre,
    const int* __restrict__ esrc, const int* __restrict__ edst,
    const float* __restrict__ ea,
    const float* __restrict__ a_src, const float* __restrict__ a_dst,
    const float* __restrict__ We, const float* __restrict__ ae,
    float* __restrict__ galpha, int* __restrict__ gsrcb, int* __restrict__ goffb) {
    __shared__ float sh_ssrc[400];
    __shared__ float sh_sdst[400];
    __shared__ float sh_alS[EMAX*8];
    __shared__ float sh_den[400];
    __shared__ float sh_av[1024];
    __shared__ float sh_weae[8];
    __shared__ float sh_easum[52];
    __shared__ int   sh_amaxi[400];
    __shared__ int   sh_srcS[EMAX];
    __shared__ int   sh_dstS[EMAX];
    __shared__ int   sh_cnt[52];
    __shared__ int   sh_off[52];
    __shared__ int   sh_cur[52];

    const int g = blockIdx.x;
    const int nb = g * NODES;
    const int eb = g * EPG;
    const int tid = threadIdx.x;
    const int lane = tid & 31, wid = tid >> 5;
    const int ECNT = LOOPS ? (EPG + NODES) : EPG;

    for (int i = tid; i < 400; i += 256) { sh_den[i] = 0.f; sh_amaxi[i] = 0; }
    if (tid < NODES) { sh_cnt[tid] = 0; sh_easum[tid] = 0.f; sh_cur[tid] = 0; }
    for (int i = tid; i < 512; i += 256) {
        sh_av[i] = a_src[i];
        sh_av[512 + i] = a_dst[i];
    }
    if (tid < 8) {
        float s = 0.f;
#pragma unroll
        for (int c = 0; c < 64; c++) s += We[tid * 64 + c] * ae[tid * 64 + c];
        sh_weae[tid] = s;
    }
    __syncthreads();

    for (int e = tid; e < EPG; e += 256) {
        int d = edst[eb + e] - nb;
        atomicAdd(&sh_cnt[d], 1);
        atomicAdd(&sh_easum[d], ea[eb + e]);
    }
    __syncthreads();

    // per-(node,head) scores: warp per node, h read from global once
    for (int n = wid; n < NODES; n += 8) {
        const float4* hr = (const float4*)(hpre + (size_t)(nb + n) * FDIM);
#pragma unroll
        for (int k = 0; k < 4; k++) {
            float4 v = hr[lane + 32 * k];
            int f = 4 * lane + 128 * k;
            float4 as = *(const float4*)(sh_av + f);
            float4 ad = *(const float4*)(sh_av + 512 + f);
            float s1 = v.x*as.x + v.y*as.y + v.z*as.z + v.w*as.w;
            float s2 = v.x*ad.x + v.y*ad.y + v.z*ad.z + v.w*ad.w;
#pragma unroll
            for (int o = 8; o > 0; o >>= 1) {
                s1 += __shfl_xor_sync(0xffffffffu, s1, o);
                s2 += __shfl_xor_sync(0xffffffffu, s2, o);
            }
            if ((lane & 15) == 0) {
                int head = 2 * k + (lane >> 4);
                sh_ssrc[n * 8 + head] = s1;
                sh_sdst[n * 8 + head] = s2;
            }
        }
    }
    __syncthreads();

    if (tid == 0) {
        int o = 0;
        for (int n = 0; n < NODES; n++) { sh_off[n] = o; o += sh_cnt[n] + (LOOPS ? 1 : 0); }
    }
    __syncthreads();

    for (int e = tid; e < ECNT; e += 256) {
        int sl, dl; float eav;
        if (e < EPG) { sl = esrc[eb + e] - nb; dl = edst[eb + e] - nb; eav = ea[eb + e]; }
        else { sl = dl = e - EPG; eav = sh_easum[dl] / fmaxf((float)sh_cnt[dl], 1.f); }
        int pos = sh_off[dl] + atomicAdd(&sh_cur[dl], 1);
        sh_srcS[pos] = sl; sh_dstS[pos] = dl;
#pragma unroll
        for (int h = 0; h < 8; h++) {
            float al = sh_ssrc[sl * 8 + h] + sh_sdst[dl * 8 + h] + eav * sh_weae[h];
            al = al > 0.f ? al : 0.2f * al;
            sh_alS[pos * 8 + h] = al;
            atomicMax(&sh_amaxi[dl * 8 + h], __float_as_int(al));
        }
    }
    __syncthreads();

    for (int i = tid; i < ECNT; i += 256) {
        int dl = sh_dstS[i];
#pragma unroll
        for (int h = 0; h < 8; h++) {
            float p = expf(sh_alS[i * 8 + h] - __int_as_float(sh_amaxi[dl * 8 + h]));
            sh_alS[i * 8 + h] = p;
            atomicAdd(&sh_den[dl * 8 + h], p);
        }
    }
    __syncthreads();
    for (int i = tid; i < 400; i += 256) sh_den[i] = 1.f / (sh_den[i] + 1e-16f);
    __syncthreads();

    // write normalized alpha + sorted src + offsets to global scratch
    float* ga = galpha + (size_t)g * EMAX * 8;
    int* gs = gsrcb + (size_t)g * EMAX;
    for (int i = tid; i < ECNT; i += 256) {
        int dl = sh_dstS[i];
        float4 o0, o1;
        o0.x = sh_alS[i*8+0] * sh_den[dl*8+0];
        o0.y = sh_alS[i*8+1] * sh_den[dl*8+1];
        o0.z = sh_alS[i*8+2] * sh_den[dl*8+2];
        o0.w = sh_alS[i*8+3] * sh_den[dl*8+3];
        o1.x = sh_alS[i*8+4] * sh_den[dl*8+4];
        o1.y = sh_alS[i*8+5] * sh_den[dl*8+5];
        o1.z = sh_alS[i*8+6] * sh_den[dl*8+6];
        o1.w = sh_alS[i*8+7] * sh_den[dl*8+7];
        ((float4*)(ga + i * 8))[0] = o0;
        ((float4*)(ga + i * 8))[1] = o1;
        gs[i] = sh_srcS[i];
    }
    if (tid < NODES) goffb[g * 51 + tid] = sh_off[tid];
    if (tid == NODES) goffb[g * 51 + NODES] = ECNT;
}

// ---------------- GAT kernel B: aggregation (graph x 128-feature slice) ----------
__global__ void __launch_bounds__(256) gat_aggr(
    const float* __restrict__ hpre,
    const float* __restrict__ galpha, const int* __restrict__ gsrcb,
    const int* __restrict__ goffb,
    const float* __restrict__ bias, float* __restrict__ xout) {
    __shared__ float sh_hs[NODES * 128];   // 25.6 KB
    __shared__ float sh_al[EMAX * 2];
    __shared__ int   sh_src[EMAX];
    __shared__ int   sh_off[51];

    const int sl = blockIdx.x;     // 0..3
    const int g = blockIdx.y;
    const int nb = g * NODES;
    const int tid = threadIdx.x;
    const int f = tid & 127, half = tid >> 7;
    const int ECNT = goffb[g * 51 + NODES];

    for (int i = tid; i < NODES * 128; i += 256) {
        int n = i >> 7, ff = i & 127;
        sh_hs[i] = hpre[(size_t)(nb + n) * FDIM + sl * 128 + ff];
    }
    const float* ga = galpha + (size_t)g * EMAX * 8 + sl * 2;
    const int* gs = gsrcb + (size_t)g * EMAX;
    for (int i = tid; i < ECNT; i += 256) {
        sh_al[i * 2]     = ga[i * 8];
        sh_al[i * 2 + 1] = ga[i * 8 + 1];
        sh_src[i] = gs[i];
    }
    if (tid <= NODES) sh_off[tid] = goffb[g * 51 + tid];
    __syncthreads();

    const int hsel = f >> 6;
    const float bv = bias[sl * 128 + f];
    for (int n = half; n < NODES; n += 2) {
        float acc = 0.f;
        const int beg = sh_off[n], end = sh_off[n + 1];
        for (int j = beg; j < end; j++)
            acc += sh_al[j * 2 + hsel] * sh_hs[sh_src[j] * 128 + f];
        xout[(size_t)(nb + n) * FDIM + sl * 128 + f] = fmaxf(acc + bv, 0.f);
    }
}

// ---------------- mean pool ----------------
__global__ void pool_k(const float* __restrict__ x3, float* __restrict__ gemb) {
    int b = blockIdx.x;
    int f = blockIdx.y * 128 + threadIdx.x;
    float s = 0.f;
#pragma unroll 10
    for (int n = 0; n < NODES; n++) s += x3[(size_t)(b * NODES + n) * FDIM + f];
    gemb[b * FDIM + f] = s * (1.f / 50.f);
}

// ---------------- build combined ----------------
__global__ void gather_k(const float* __restrict__ x3, const float* __restrict__ gemb,
                         float* __restrict__ comb) {
    int r = blockIdx.x;
    int b = r / 5, t = r - b * 5;
    for (int i = threadIdx.x; i < GRUI; i += 256)
        comb[(size_t)r * GRUI + i] =
            (i < 512) ? x3[(size_t)(b * NODES + t) * FDIM + i] : gemb[b * FDIM + i - 512];
}

// ---------------- GRU: GH = h @ Whh ----------------
__global__ void gru_gh_k(const float* __restrict__ h, const float* __restrict__ Whh,
                         float* __restrict__ GH) {
    __shared__ float hs[8 * GRUH];
    int b0 = blockIdx.x * 8;
    int tid = threadIdx.x;
    for (int i = tid; i < 8 * GRUH; i += 384) hs[i] = h[b0 * GRUH + i];
    __syncthreads();
    float acc[8];
#pragma unroll
    for (int r = 0; r < 8; r++) acc[r] = 0.f;
    for (int k = 0; k < GRUH; k++) {
        float w = Whh[k * G3 + tid];
#pragma unroll
        for (int r = 0; r < 8; r++) acc[r] += hs[r * GRUH + k] * w;
    }
#pragma unroll
    for (int r = 0; r < 8; r++) GH[(b0 + r) * G3 + tid] = acc[r];
}

// ---------------- GRU gate math ----------------
__global__ void gru_gate_k(const float* __restrict__ GI, int t,
                           const float* __restrict__ GHb, const float* __restrict__ hprev,
                           const float* __restrict__ bih, const float* __restrict__ bhh,
                           float* __restrict__ hnew, float* __restrict__ gout,
                           float* __restrict__ hlast) {
    int b = blockIdx.x, j = threadIdx.x;
    const float* gi = GI + (size_t)(b * NA + t) * G3;
    const float* gh = GHb + (size_t)b * G3;
    float ir = gi[j] + bih[j];
    float iz = gi[j + 128] + bih[j + 128];
    float in_ = gi[j + 256] + bih[j + 256];
    float hr = gh[j] + bhh[j];
    float hz = gh[j + 128] + bhh[j + 128];
    float hn = gh[j + 256] + bhh[j + 256];
    float r = 1.f / (1.f + expf(-(ir + hr)));
    float z = 1.f / (1.f + expf(-(iz + hz)));
    float nn = tanhf(in_ + r * hn);
    float hp = hprev[b * GRUH + j];
    float h = (1.f - z) * nn + z * hp;
    hnew[b * GRUH + j] = h;
    gout[(size_t)(b * NA + t) * GRUH + j] = h;
    if (hlast) hlast[b * GRUH + j] = h;
}

// ---------------- FC head ----------------
__global__ void fc_k(const float* __restrict__ gout, const float* __restrict__ W1,
                     const float* __restrict__ b1, const float* __restrict__ W2,
                     const float* __restrict__ b2, const float* __restrict__ ls,
                     float* __restrict__ out) {
    __shared__ float g[128];
    __shared__ float f1[64];
    int r = blockIdx.x, tid = threadIdx.x;
    g[tid] = gout[(size_t)r * GRUH + tid];
    g[tid + 64] = gout[(size_t)r * GRUH + tid + 64];
    __syncthreads();
    float acc = b1[tid];
#pragma unroll 8
    for (int k = 0; k < 128; k++) acc += g[k] * W1[k * 64 + tid];
    f1[tid] = acc > 0.f ? acc : 0.f;
    __syncthreads();
    if (tid < 3) {
        float a2 = b2[tid];
#pragma unroll
        for (int k = 0; k < 64; k++) a2 += f1[k] * W2[k * 3 + tid];
        out[r * 3 + tid] = a2;
        float l = ls[tid];
        l = fminf(fmaxf(l, -20.f), 2.f);
        out[NGRAPH * NA * 3 + r * 3 + tid] = expf(l);
    }
}

// ---------------- launch ----------------
extern "C" void kernel_launch(void* const* d_in, const int* in_sizes, int n_in,
                              void* d_out, int out_size) {
    const float* x      = (const float*)d_in[0];
    const int*   ei     = (const int*)d_in[1];
    const float* ea     = (const float*)d_in[2];
    const float* hid0   = (const float*)d_in[3];
    const float* W1     = (const float*)d_in[4];
    const float* a_s1   = (const float*)d_in[5];
    const float* a_d1   = (const float*)d_in[6];
    const float* We1    = (const float*)d_in[7];
    const float* ae1    = (const float*)d_in[8];
    const float* b1     = (const float*)d_in[9];
    const float* W2     = (const float*)d_in[10];
    const float* a_s2   = (const float*)d_in[11];
    const float* a_d2   = (const float*)d_in[12];
    const float* We2    = (const float*)d_in[13];
    const float* ae2    = (const float*)d_in[14];
    const float* b2     = (const float*)d_in[15];
    const float* W3     = (const float*)d_in[16];
    const float* a_s3   = (const float*)d_in[17];
    const float* a_d3   = (const float*)d_in[18];
    const float* We3    = (const float*)d_in[19];
    const float* ae3    = (const float*)d_in[20];
    const float* b3     = (const float*)d_in[21];
    const float* Wih    = (const float*)d_in[22];
    const float* Whh    = (const float*)d_in[23];
    const float* bih    = (const float*)d_in[24];
    const float* bhh    = (const float*)d_in[25];
    const float* fc1W   = (const float*)d_in[26];
    const float* fc1b   = (const float*)d_in[27];
    const float* fc2W   = (const float*)d_in[28];
    const float* fc2b   = (const float*)d_in[29];
    const float* logstd = (const float*)d_in[30];
    float* out = (float*)d_out;

    float *bufA, *bufB, *gemb, *comb, *GI, *GHb, *h0b, *h1b, *gout, *alphab;
    int *srcb, *offb;
    __nv_bfloat16 *Ah, *Al, *Bh, *Bl;
    cudaGetSymbolAddress((void**)&bufA, g_bufA);
    cudaGetSymbolAddress((void**)&bufB, g_bufB);
    cudaGetSymbolAddress((void**)&gemb, g_gemb);
    cudaGetSymbolAddress((void**)&comb, g_comb);
    cudaGetSymbolAddress((void**)&GI,   g_GI);
    cudaGetSymbolAddress((void**)&GHb,  g_GHbuf);
    cudaGetSymbolAddress((void**)&h0b,  g_h0);
    cudaGetSymbolAddress((void**)&h1b,  g_h1);
    cudaGetSymbolAddress((void**)&gout, g_gruout);
    cudaGetSymbolAddress((void**)&alphab, g_alpha);
    cudaGetSymbolAddress((void**)&srcb, g_srcb);
    cudaGetSymbolAddress((void**)&offb, g_offb);
    cudaGetSymbolAddress((void**)&Ah, g_Ah);
    cudaGetSymbolAddress((void**)&Al, g_Al);
    cudaGetSymbolAddress((void**)&Bh, g_Bh);
    cudaGetSymbolAddress((void**)&Bl, g_Bl);

    cudaFuncSetAttribute((const void*)gemm_mma,
                         cudaFuncAttributeMaxDynamicSharedMemorySize, GEMM_SMEM);

    const int* esrc = ei;
    const int* edst = ei + NE;

    // layer 1
    lin1_k<<<(NN * FDIM) / 256, 256>>>(x, W1, bufA);
    gat_attn<false><<<NGRAPH, 256>>>(bufA, esrc, edst, ea, a_s1, a_d1, We1, ae1,
                                     alphab, srcb, offb);
    gat_aggr<<<dim3(4, NGRAPH), 256>>>(bufA, alphab, srcb, offb, b1, bufB);
    // layer 2
    splitT_k<<<(FDIM * FDIM + 255) / 256, 256>>>(W2, Bh, Bl, FDIM, FDIM);
    split_k<<<(NN * FDIM / 4 + 255) / 256, 256>>>(bufB, Ah, Al, NN * FDIM / 4);
    gemm_mma<<<dim3(FDIM / 128, NN / 128), 256, GEMM_SMEM>>>(Ah, Al, Bh, Bl, bufA,
                                                             NN, FDIM, FDIM);
    gat_attn<true><<<NGRAPH, 256>>>(bufA, esrc, edst, ea, a_s2, a_d2, We2, ae2,
                                    alphab, srcb, offb);
    gat_aggr<<<dim3(4, NGRAPH), 256>>>(bufA, alphab, srcb, offb, b2, bufB);
    // layer 3
    splitT_k<<<(FDIM * FDIM + 255) / 256, 256>>>(W3, Bh, Bl, FDIM, FDIM);
    split_k<<<(NN * FDIM / 4 + 255) / 256, 256>>>(bufB, Ah, Al, NN * FDIM / 4);
    gemm_mma<<<dim3(FDIM / 128, NN / 128), 256, GEMM_SMEM>>>(Ah, Al, Bh, Bl, bufA,
                                                             NN, FDIM, FDIM);
    gat_attn<true><<<NGRAPH, 256>>>(bufA, esrc, edst, ea, a_s3, a_d3, We3, ae3,
                                    alphab, srcb, offb);
    gat_aggr<<<dim3(4, NGRAPH), 256>>>(bufA, alphab, srcb, offb, b3, bufB);
    // pooling + GRU input GEMM
    pool_k<<<dim3(NGRAPH, FDIM / 128), 128>>>(bufB, gemb);
    gather_k<<<NGRAPH * NA, 256>>>(bufB, gemb, comb);
    splitT_k<<<(GRUI * G3 + 255) / 256, 256>>>(Wih, Bh, Bl, GRUI, G3);
    split_k<<<(NGRAPH * NA * GRUI / 4 + 255) / 256, 256>>>(comb, Ah, Al,
                                                           NGRAPH * NA * GRUI / 4);
    gemm_mma<<<dim3(G3 / 128, (NGRAPH * NA) / 128), 256, GEMM_SMEM>>>(
        Ah, Al, Bh, Bl, GI, NGRAPH * NA, G3, GRUI);
    // GRU recurrence
    cudaMemcpyAsync(h0b, hid0, (size_t)NGRAPH * GRUH * sizeof(float),
                    cudaMemcpyDeviceToDevice);
    for (int t = 0; t < NA; t++) {
        float* hc = (t & 1) ? h1b : h0b;
        float* hn = (t & 1) ? h0b : h1b;
        gru_gh_k<<<NGRAPH / 8, G3>>>(hc, Whh, GHb);
        gru_gate_k<<<NGRAPH, GRUH>>>(GI, t, GHb, hc, bih, bhh, hn, gout,
                                     (t == NA - 1) ? (out + NGRAPH * NA * 3 * 2) : nullptr);
    }
    fc_k<<<NGRAPH * NA, 64>>>(gout, fc1W, fc1b, fc2W, fc2b, logstd, out);
}

// round 9
// speedup vs baseline: 1.3528x; 1.0327x over previous
#include <cuda_runtime.h>
#include <cuda_bf16.h>
#include <cstdint>

#define NODES 50
#define EPG   400
#define NGRAPH 512
#define NN    (NGRAPH*NODES)   // 25600
#define NE    (NGRAPH*EPG)     // 204800
#define FDIM  512
#define HEADS 8
#define CH    64
#define NA    5
#define GRUH  128
#define GRUI  1024
#define G3    384
#define EMAX  456              // padded per-graph edge capacity (450 used)

// ---------------- scratch (static device globals; no allocation) ----------------
__device__ float g_bufA[NN*FDIM];
__device__ float g_bufB[NN*FDIM];
__device__ __nv_bfloat16 g_Ah[NN*FDIM];
__device__ __nv_bfloat16 g_Al[NN*FDIM];
__device__ __nv_bfloat16 g_Bh[GRUI*G3 > FDIM*FDIM ? GRUI*G3 : FDIM*FDIM];
__device__ __nv_bfloat16 g_Bl[GRUI*G3 > FDIM*FDIM ? GRUI*G3 : FDIM*FDIM];
__device__ float g_alpha[NGRAPH*EMAX*HEADS];
__device__ int   g_srcb[NGRAPH*EMAX];
__device__ int   g_offb[NGRAPH*51];
__device__ float g_GI[NGRAPH*NA*G3];
__device__ float g_GHbuf[NGRAPH*G3];
__device__ float g_h0[NGRAPH*GRUH];
__device__ float g_h1[NGRAPH*GRUH];
__device__ float g_gruout[NGRAPH*NA*GRUH];

// ---------------- helpers ----------------
__device__ __forceinline__ uint32_t smem_u32(const void* p) {
    uint32_t a;
    asm("{ .reg .u64 t; cvta.to.shared.u64 t, %1; cvt.u32.u64 %0, t; }" : "=r"(a) : "l"(p));
    return a;
}
__device__ __forceinline__ void cp16(uint32_t sdst, const void* gsrc) {
    asm volatile("cp.async.cg.shared.global [%0], [%1], 16;" :: "r"(sdst), "l"(gsrc) : "memory");
}
__device__ __forceinline__ uint32_t lds32(uint32_t a) {
    uint32_t v;
    asm volatile("ld.shared.b32 %0, [%1];" : "=r"(v) : "r"(a));
    return v;
}
__device__ __forceinline__ void mma16816(float* c, uint32_t a0, uint32_t a1,
                                         uint32_t a2, uint32_t a3,
                                         uint32_t b0, uint32_t b1) {
    asm volatile(
        "mma.sync.aligned.m16n8k16.row.col.f32.bf16.bf16.f32 "
        "{%0,%1,%2,%3}, {%4,%5,%6,%7}, {%8,%9}, {%0,%1,%2,%3};"
        : "+f"(c[0]), "+f"(c[1]), "+f"(c[2]), "+f"(c[3])
        : "r"(a0), "r"(a1), "r"(a2), "r"(a3), "r"(b0), "r"(b1));
}
__device__ __forceinline__ void split1(float v, __nv_bfloat16& h, __nv_bfloat16& l) {
    h = __float2bfloat16_rn(v);
    l = __float2bfloat16_rn(v - __bfloat162float(h));
}

// W [K,N] fp32 -> Wt [N,K] bf16 hi/lo (transposed)
__global__ void splitT_k(const float* __restrict__ W, __nv_bfloat16* __restrict__ hi,
                         __nv_bfloat16* __restrict__ lo, int K, int N) {
    int idx = blockIdx.x * 256 + threadIdx.x;
    if (idx >= N * K) return;
    int n = idx / K, k = idx - n * K;
    float v = W[(size_t)k * N + n];
    __nv_bfloat16 h, l;
    split1(v, h, l);
    hi[idx] = h;
    lo[idx] = l;
}

// ---------------- HMMA bf16-split GEMM: C[M,N] = A[M,K] * B[N,K]^T ----------------
#define STAGES 3
#define PITCH 80
#define MAT_BYTES (128*PITCH)
#define STAGE_BYTES (4*MAT_BYTES)
#define GEMM_SMEM (STAGES*STAGE_BYTES)

__global__ void __launch_bounds__(256) gemm_mma(
    const __nv_bfloat16* __restrict__ Ah, const __nv_bfloat16* __restrict__ Al,
    const __nv_bfloat16* __restrict__ Bh, const __nv_bfloat16* __restrict__ Bl,
    float* __restrict__ C, int M, int N, int K) {
    extern __shared__ char sm8[];
    const uint32_t sb = smem_u32(sm8);
    const int tid = threadIdx.x;
    const int lane = tid & 31, wid = tid >> 5;
    const int wm = wid & 3, wn = wid >> 2;
    const int bm = blockIdx.y * 128, bn = blockIdx.x * 128;
    const int g = lane >> 2, tig = lane & 3;
    const int NCH = K >> 5;

    const char* pAh = (const char*)Ah;
    const char* pAl = (const char*)Al;
    const char* pBh = (const char*)Bh;
    const char* pBl = (const char*)Bl;
    const size_t rowb = (size_t)K * 2;

    auto load_stage = [&](int kc, int s) {
        uint32_t sbase = sb + s * STAGE_BYTES;
        size_t kb = (size_t)kc * 64;
#pragma unroll
        for (int i = tid; i < 512; i += 256) {
            int r = i >> 2, gg = i & 3;
            uint32_t so = sbase + r * PITCH + gg * 16;
            size_t ga = (size_t)(bm + r) * rowb + kb + gg * 16;
            size_t gb = (size_t)(bn + r) * rowb + kb + gg * 16;
            cp16(so,                 pAh + ga);
            cp16(so + MAT_BYTES,     pAl + ga);
            cp16(so + 2*MAT_BYTES,   pBh + gb);
            cp16(so + 3*MAT_BYTES,   pBl + gb);
        }
        asm volatile("cp.async.commit_group;" ::: "memory");
    };

    float acc[2][8][4];
#pragma unroll
    for (int f = 0; f < 2; f++)
#pragma unroll
        for (int nf = 0; nf < 8; nf++)
#pragma unroll
            for (int c = 0; c < 4; c++) acc[f][nf][c] = 0.f;

    load_stage(0, 0);
    load_stage(1, 1);

    for (int kc = 0; kc < NCH; kc++) {
        int s = kc % STAGES;
        asm volatile("cp.async.wait_group 1;" ::: "memory");
        __syncthreads();
        if (kc + 2 < NCH) load_stage(kc + 2, (kc + 2) % STAGES);
        else asm volatile("cp.async.commit_group;" ::: "memory");

        uint32_t aA = sb + s * STAGE_BYTES;
        uint32_t aB = aA + 2*MAT_BYTES;
#pragma unroll
        for (int kk = 0; kk < 2; kk++) {
            const uint32_t kof = kk * 32 + tig * 4;
            uint32_t ah[2][4], al[2][4];
#pragma unroll
            for (int f = 0; f < 2; f++) {
                uint32_t r0 = (uint32_t)(wm * 32 + f * 16 + g) * PITCH + kof;
                ah[f][0] = lds32(aA + r0);
                ah[f][1] = lds32(aA + r0 + 8*PITCH);
                ah[f][2] = lds32(aA + r0 + 16);
                ah[f][3] = lds32(aA + r0 + 8*PITCH + 16);
                al[f][0] = lds32(aA + MAT_BYTES + r0);
                al[f][1] = lds32(aA + MAT_BYTES + r0 + 8*PITCH);
                al[f][2] = lds32(aA + MAT_BYTES + r0 + 16);
                al[f][3] = lds32(aA + MAT_BYTES + r0 + 8*PITCH + 16);
            }
#pragma unroll
            for (int nf = 0; nf < 8; nf++) {
                uint32_t n0 = (uint32_t)(wn * 64 + nf * 8 + g) * PITCH + kof;
                uint32_t bh0 = lds32(aB + n0);
                uint32_t bh1 = lds32(aB + n0 + 16);
                uint32_t bl0 = lds32(aB + MAT_BYTES + n0);
                uint32_t bl1 = lds32(aB + MAT_BYTES + n0 + 16);
#pragma unroll
                for (int f = 0; f < 2; f++) {
                    mma16816(acc[f][nf], ah[f][0], ah[f][1], ah[f][2], ah[f][3], bh0, bh1);
                    mma16816(acc[f][nf], ah[f][0], ah[f][1], ah[f][2], ah[f][3], bl0, bl1);
                    mma16816(acc[f][nf], al[f][0], al[f][1], al[f][2], al[f][3], bh0, bh1);
                }
            }
        }
        __syncthreads();
    }

#pragma unroll
    for (int f = 0; f < 2; f++) {
        int r0 = bm + wm * 32 + f * 16 + g;
#pragma unroll
        for (int nf = 0; nf < 8; nf++) {
            int c0 = bn + wn * 64 + nf * 8 + 2 * tig;
            *(float2*)&C[(size_t)r0 * N + c0]       = make_float2(acc[f][nf][0], acc[f][nf][1]);
            *(float2*)&C[(size_t)(r0 + 8) * N + c0] = make_float2(acc[f][nf][2], acc[f][nf][3]);
        }
    }
}

// ---------------- x @ W1  (K=4) ----------------
__global__ void lin1_k(const float* __restrict__ x, const float* __restrict__ W,
                       float* __restrict__ out) {
    int idx = blockIdx.x * 256 + threadIdx.x;
    int n = idx >> 9, f = idx & 511;
    const float* xr = x + n * 4;
    out[idx] = xr[0]*W[f] + xr[1]*W[512+f] + xr[2]*W[1024+f] + xr[3]*W[1536+f];
}

// ---------------- GAT kernel A: attention (per graph, small smem, hi occ) --------
template <bool LOOPS>
__global__ void __launch_bounds__(256) gat_attn(
    const float* __restrict__ hpre,
    const int* __restrict__ esrc, const int* __restrict__ edst,
    const float* __restrict__ ea,
    const float* __restrict__ a_src, const float* __restrict__ a_dst,
    const float* __restrict__ We, const float* __restrict__ ae,
    float* __restrict__ galpha, int* __restrict__ gsrcb, int* __restrict__ goffb) {
    __shared__ float sh_ssrc[400];
    __shared__ float sh_sdst[400];
    __shared__ float sh_alS[EMAX*8];
    __shared__ float sh_den[400];
    __shared__ float sh_av[1024];
    __shared__ float sh_weae[8];
    __shared__ float sh_easum[52];
    __shared__ int   sh_amaxi[400];
    __shared__ int   sh_srcS[EMAX];
    __shared__ int   sh_dstS[EMAX];
    __shared__ int   sh_cnt[52];
    __shared__ int   sh_off[52];
    __shared__ int   sh_cur[52];

    const int g = blockIdx.x;
    const int nb = g * NODES;
    const int eb = g * EPG;
    const int tid = threadIdx.x;
    const int lane = tid & 31, wid = tid >> 5;
    const int ECNT = LOOPS ? (EPG + NODES) : EPG;

    for (int i = tid; i < 400; i += 256) { sh_den[i] = 0.f; sh_amaxi[i] = 0; }
    if (tid < NODES) { sh_cnt[tid] = 0; sh_easum[tid] = 0.f; sh_cur[tid] = 0; }
    for (int i = tid; i < 512; i += 256) {
        sh_av[i] = a_src[i];
        sh_av[512 + i] = a_dst[i];
    }
    if (tid < 8) {
        float s = 0.f;
#pragma unroll
        for (int c = 0; c < 64; c++) s += We[tid * 64 + c] * ae[tid * 64 + c];
        sh_weae[tid] = s;
    }
    __syncthreads();

    for (int e = tid; e < EPG; e += 256) {
        int d = edst[eb + e] - nb;
        atomicAdd(&sh_cnt[d], 1);
        atomicAdd(&sh_easum[d], ea[eb + e]);
    }
    __syncthreads();

    // per-(node,head) scores: warp per node, h read from global once
    for (int n = wid; n < NODES; n += 8) {
        const float4* hr = (const float4*)(hpre + (size_t)(nb + n) * FDIM);
#pragma unroll
        for (int k = 0; k < 4; k++) {
            float4 v = hr[lane + 32 * k];
            int f = 4 * lane + 128 * k;
            float4 as = *(const float4*)(sh_av + f);
            float4 ad = *(const float4*)(sh_av + 512 + f);
            float s1 = v.x*as.x + v.y*as.y + v.z*as.z + v.w*as.w;
            float s2 = v.x*ad.x + v.y*ad.y + v.z*ad.z + v.w*ad.w;
#pragma unroll
            for (int o = 8; o > 0; o >>= 1) {
                s1 += __shfl_xor_sync(0xffffffffu, s1, o);
                s2 += __shfl_xor_sync(0xffffffffu, s2, o);
            }
            if ((lane & 15) == 0) {
                int head = 2 * k + (lane >> 4);
                sh_ssrc[n * 8 + head] = s1;
                sh_sdst[n * 8 + head] = s2;
            }
        }
    }
    __syncthreads();

    if (tid == 0) {
        int o = 0;
        for (int n = 0; n < NODES; n++) { sh_off[n] = o; o += sh_cnt[n] + (LOOPS ? 1 : 0); }
    }
    __syncthreads();

    for (int e = tid; e < ECNT; e += 256) {
        int sl, dl; float eav;
        if (e < EPG) { sl = esrc[eb + e] - nb; dl = edst[eb + e] - nb; eav = ea[eb + e]; }
        else { sl = dl = e - EPG; eav = sh_easum[dl] / fmaxf((float)sh_cnt[dl], 1.f); }
        int pos = sh_off[dl] + atomicAdd(&sh_cur[dl], 1);
        sh_srcS[pos] = sl; sh_dstS[pos] = dl;
#pragma unroll
        for (int h = 0; h < 8; h++) {
            float al = sh_ssrc[sl * 8 + h] + sh_sdst[dl * 8 + h] + eav * sh_weae[h];
            al = al > 0.f ? al : 0.2f * al;
            sh_alS[pos * 8 + h] = al;
            atomicMax(&sh_amaxi[dl * 8 + h], __float_as_int(al));
        }
    }
    __syncthreads();

    for (int i = tid; i < ECNT; i += 256) {
        int dl = sh_dstS[i];
#pragma unroll
        for (int h = 0; h < 8; h++) {
            float p = expf(sh_alS[i * 8 + h] - __int_as_float(sh_amaxi[dl * 8 + h]));
            sh_alS[i * 8 + h] = p;
            atomicAdd(&sh_den[dl * 8 + h], p);
        }
    }
    __syncthreads();
    for (int i = tid; i < 400; i += 256) sh_den[i] = 1.f / (sh_den[i] + 1e-16f);
    __syncthreads();

    // write normalized alpha + sorted src + offsets to global scratch
    float* ga = galpha + (size_t)g * EMAX * 8;
    int* gs = gsrcb + (size_t)g * EMAX;
    for (int i = tid; i < ECNT; i += 256) {
        int dl = sh_dstS[i];
        float4 o0, o1;
        o0.x = sh_alS[i*8+0] * sh_den[dl*8+0];
        o0.y = sh_alS[i*8+1] * sh_den[dl*8+1];
        o0.z = sh_alS[i*8+2] * sh_den[dl*8+2];
        o0.w = sh_alS[i*8+3] * sh_den[dl*8+3];
        o1.x = sh_alS[i*8+4] * sh_den[dl*8+4];
        o1.y = sh_alS[i*8+5] * sh_den[dl*8+5];
        o1.z = sh_alS[i*8+6] * sh_den[dl*8+6];
        o1.w = sh_alS[i*8+7] * sh_den[dl*8+7];
        ((float4*)(ga + i * 8))[0] = o0;
        ((float4*)(ga + i * 8))[1] = o1;
        gs[i] = sh_srcS[i];
    }
    if (tid < NODES) goffb[g * 51 + tid] = sh_off[tid];
    if (tid == NODES) goffb[g * 51 + NODES] = ECNT;
}

// ---------------- GAT kernel B: aggregation (graph x 128-feature slice) ----------
// OUTBF16: write bf16 hi/lo (feeds next GEMM) instead of fp32
template <bool OUTBF16>
__global__ void __launch_bounds__(256) gat_aggr(
    const float* __restrict__ hpre,
    const float* __restrict__ galpha, const int* __restrict__ gsrcb,
    const int* __restrict__ goffb,
    const float* __restrict__ bias, float* __restrict__ xout,
    __nv_bfloat16* __restrict__ outh, __nv_bfloat16* __restrict__ outl) {
    __shared__ float sh_hs[NODES * 128];   // 25.6 KB
    __shared__ float sh_al[EMAX * 2];
    __shared__ int   sh_src[EMAX];
    __shared__ int   sh_off[51];

    const int sl = blockIdx.x;     // 0..3
    const int g = blockIdx.y;
    const int nb = g * NODES;
    const int tid = threadIdx.x;
    const int f = tid & 127, half = tid >> 7;
    const int ECNT = goffb[g * 51 + NODES];

    for (int i = tid; i < NODES * 128; i += 256) {
        int n = i >> 7, ff = i & 127;
        sh_hs[i] = hpre[(size_t)(nb + n) * FDIM + sl * 128 + ff];
    }
    const float* ga = galpha + (size_t)g * EMAX * 8 + sl * 2;
    const int* gs = gsrcb + (size_t)g * EMAX;
    for (int i = tid; i < ECNT; i += 256) {
        sh_al[i * 2]     = ga[i * 8];
        sh_al[i * 2 + 1] = ga[i * 8 + 1];
        sh_src[i] = gs[i];
    }
    if (tid <= NODES) sh_off[tid] = goffb[g * 51 + tid];
    __syncthreads();

    const int hsel = f >> 6;
    const float bv = bias[sl * 128 + f];
    for (int n = half; n < NODES; n += 2) {
        float acc = 0.f;
        const int beg = sh_off[n], end = sh_off[n + 1];
        for (int j = beg; j < end; j++)
            acc += sh_al[j * 2 + hsel] * sh_hs[sh_src[j] * 128 + f];
        float v = fmaxf(acc + bv, 0.f);
        size_t idx = (size_t)(nb + n) * FDIM + sl * 128 + f;
        if (OUTBF16) {
            __nv_bfloat16 h, l;
            split1(v, h, l);
            outh[idx] = h;
            outl[idx] = l;
        } else {
            xout[idx] = v;
        }
    }
}

// ---------------- mean pool -> bf16 hi/lo graph-emb half of GRU operand ----------
__global__ void pool_k(const float* __restrict__ x3, __nv_bfloat16* __restrict__ Ah,
                       __nv_bfloat16* __restrict__ Al) {
    int b = blockIdx.x;
    int f = blockIdx.y * 128 + threadIdx.x;
    float s = 0.f;
#pragma unroll 10
    for (int n = 0; n < NODES; n++) s += x3[(size_t)(b * NODES + n) * FDIM + f];
    s *= (1.f / 50.f);
    __nv_bfloat16 h, l;
    split1(s, h, l);
#pragma unroll
    for (int t = 0; t < NA; t++) {
        Ah[(size_t)(b * NA + t) * GRUI + 512 + f] = h;
        Al[(size_t)(b * NA + t) * GRUI + 512 + f] = l;
    }
}

// ---------------- agent rows -> bf16 hi/lo agent half of GRU operand -------------
__global__ void agent_k(const float* __restrict__ x3, __nv_bfloat16* __restrict__ Ah,
                        __nv_bfloat16* __restrict__ Al) {
    int r = blockIdx.x;           // b*5 + t
    int b = r / 5, t = r - b * 5;
    for (int f = threadIdx.x; f < 512; f += 128) {
        float v = x3[(size_t)(b * NODES + t) * FDIM + f];
        __nv_bfloat16 h, l;
        split1(v, h, l);
        Ah[(size_t)r * GRUI + f] = h;
        Al[(size_t)r * GRUI + f] = l;
    }
}

// ---------------- GRU: GH = h @ Whh ----------------
__global__ void gru_gh_k(const float* __restrict__ h, const float* __restrict__ Whh,
                         float* __restrict__ GH) {
    __shared__ float hs[8 * GRUH];
    int b0 = blockIdx.x * 8;
    int tid = threadIdx.x;
    for (int i = tid; i < 8 * GRUH; i += 384) hs[i] = h[b0 * GRUH + i];
    __syncthreads();
    float acc[8];
#pragma unroll
    for (int r = 0; r < 8; r++) acc[r] = 0.f;
    for (int k = 0; k < GRUH; k++) {
        float w = Whh[k * G3 + tid];
#pragma unroll
        for (int r = 0; r < 8; r++) acc[r] += hs[r * GRUH + k] * w;
    }
#pragma unroll
    for (int r = 0; r < 8; r++) GH[(b0 + r) * G3 + tid] = acc[r];
}

// ---------------- GRU gate math ----------------
__global__ void gru_gate_k(const float* __restrict__ GI, int t,
                           const float* __restrict__ GHb, const float* __restrict__ hprev,
                           const float* __restrict__ bih, const float* __restrict__ bhh,
                           float* __restrict__ hnew, float* __restrict__ gout,
                           float* __restrict__ hlast) {
    int b = blockIdx.x, j = threadIdx.x;
    const float* gi = GI + (size_t)(b * NA + t) * G3;
    const float* gh = GHb + (size_t)b * G3;
    float ir = gi[j] + bih[j];
    float iz = gi[j + 128] + bih[j + 128];
    float in_ = gi[j + 256] + bih[j + 256];
    float hr = gh[j] + bhh[j];
    float hz = gh[j + 128] + bhh[j + 128];
    float hn = gh[j + 256] + bhh[j + 256];
    float r = 1.f / (1.f + expf(-(ir + hr)));
    float z = 1.f / (1.f + expf(-(iz + hz)));
    float nn = tanhf(in_ + r * hn);
    float hp = hprev[b * GRUH + j];
    float h = (1.f - z) * nn + z * hp;
    hnew[b * GRUH + j] = h;
    gout[(size_t)(b * NA + t) * GRUH + j] = h;
    if (hlast) hlast[b * GRUH + j] = h;
}

// ---------------- FC head ----------------
__global__ void fc_k(const float* __restrict__ gout, const float* __restrict__ W1,
                     const float* __restrict__ b1, const float* __restrict__ W2,
                     const float* __restrict__ b2, const float* __restrict__ ls,
                     float* __restrict__ out) {
    __shared__ float g[128];
    __shared__ float f1[64];
    int r = blockIdx.x, tid = threadIdx.x;
    g[tid] = gout[(size_t)r * GRUH + tid];
    g[tid + 64] = gout[(size_t)r * GRUH + tid + 64];
    __syncthreads();
    float acc = b1[tid];
#pragma unroll 8
    for (int k = 0; k < 128; k++) acc += g[k] * W1[k * 64 + tid];
    f1[tid] = acc > 0.f ? acc : 0.f;
    __syncthreads();
    if (tid < 3) {
        float a2 = b2[tid];
#pragma unroll
        for (int k = 0; k < 64; k++) a2 += f1[k] * W2[k * 3 + tid];
        out[r * 3 + tid] = a2;
        float l = ls[tid];
        l = fminf(fmaxf(l, -20.f), 2.f);
        out[NGRAPH * NA * 3 + r * 3 + tid] = expf(l);
    }
}

// ---------------- launch ----------------
extern "C" void kernel_launch(void* const* d_in, const int* in_sizes, int n_in,
                              void* d_out, int out_size) {
    const float* x      = (const float*)d_in[0];
    const int*   ei     = (const int*)d_in[1];
    const float* ea     = (const float*)d_in[2];
    const float* hid0   = (const float*)d_in[3];
    const float* W1     = (const float*)d_in[4];
    const float* a_s1   = (const float*)d_in[5];
    const float* a_d1   = (const float*)d_in[6];
    const float* We1    = (const float*)d_in[7];
    const float* ae1    = (const float*)d_in[8];
    const float* b1     = (const float*)d_in[9];
    const float* W2     = (const float*)d_in[10];
    const float* a_s2   = (const float*)d_in[11];
    const float* a_d2   = (const float*)d_in[12];
    const float* We2    = (const float*)d_in[13];
    const float* ae2    = (const float*)d_in[14];
    const float* b2     = (const float*)d_in[15];
    const float* W3     = (const float*)d_in[16];
    const float* a_s3   = (const float*)d_in[17];
    const float* a_d3   = (const float*)d_in[18];
    const float* We3    = (const float*)d_in[19];
    const float* ae3    = (const float*)d_in[20];
    const float* b3     = (const float*)d_in[21];
    const float* Wih    = (const float*)d_in[22];
    const float* Whh    = (const float*)d_in[23];
    const float* bih    = (const float*)d_in[24];
    const float* bhh    = (const float*)d_in[25];
    const float* fc1W   = (const float*)d_in[26];
    const float* fc1b   = (const float*)d_in[27];
    const float* fc2W   = (const float*)d_in[28];
    const float* fc2b   = (const float*)d_in[29];
    const float* logstd = (const float*)d_in[30];
    float* out = (float*)d_out;

    float *bufA, *bufB, *GI, *GHb, *h0b, *h1b, *gout, *alphab;
    int *srcb, *offb;
    __nv_bfloat16 *Ah, *Al, *Bh, *Bl;
    cudaGetSymbolAddress((void**)&bufA, g_bufA);
    cudaGetSymbolAddress((void**)&bufB, g_bufB);
    cudaGetSymbolAddress((void**)&GI,   g_GI);
    cudaGetSymbolAddress((void**)&GHb,  g_GHbuf);
    cudaGetSymbolAddress((void**)&h0b,  g_h0);
    cudaGetSymbolAddress((void**)&h1b,  g_h1);
    cudaGetSymbolAddress((void**)&gout, g_gruout);
    cudaGetSymbolAddress((void**)&alphab, g_alpha);
    cudaGetSymbolAddress((void**)&srcb, g_srcb);
    cudaGetSymbolAddress((void**)&offb, g_offb);
    cudaGetSymbolAddress((void**)&Ah, g_Ah);
    cudaGetSymbolAddress((void**)&Al, g_Al);
    cudaGetSymbolAddress((void**)&Bh, g_Bh);
    cudaGetSymbolAddress((void**)&Bl, g_Bl);

    cudaFuncSetAttribute((const void*)gemm_mma,
                         cudaFuncAttributeMaxDynamicSharedMemorySize, GEMM_SMEM);

    const int* esrc = ei;
    const int* edst = ei + NE;

    // layer 1 -> bf16 hi/lo directly
    lin1_k<<<(NN * FDIM) / 256, 256>>>(x, W1, bufA);
    gat_attn<false><<<NGRAPH, 256>>>(bufA, esrc, edst, ea, a_s1, a_d1, We1, ae1,
                                     alphab, srcb, offb);
    gat_aggr<true><<<dim3(4, NGRAPH), 256>>>(bufA, alphab, srcb, offb, b1,
                                             nullptr, Ah, Al);
    // layer 2
    splitT_k<<<(FDIM * FDIM + 255) / 256, 256>>>(W2, Bh, Bl, FDIM, FDIM);
    gemm_mma<<<dim3(FDIM / 128, NN / 128), 256, GEMM_SMEM>>>(Ah, Al, Bh, Bl, bufA,
                                                             NN, FDIM, FDIM);
    gat_attn<true><<<NGRAPH, 256>>>(bufA, esrc, edst, ea, a_s2, a_d2, We2, ae2,
                                    alphab, srcb, offb);
    gat_aggr<true><<<dim3(4, NGRAPH), 256>>>(bufA, alphab, srcb, offb, b2,
                                             nullptr, Ah, Al);
    // layer 3 -> fp32 (feeds pool/agent)
    splitT_k<<<(FDIM * FDIM + 255) / 256, 256>>>(W3, Bh, Bl, FDIM, FDIM);
    gemm_mma<<<dim3(FDIM / 128, NN / 128), 256, GEMM_SMEM>>>(Ah, Al, Bh, Bl, bufA,
                                                             NN, FDIM, FDIM);
    gat_attn<true><<<NGRAPH, 256>>>(bufA, esrc, edst, ea, a_s3, a_d3, We3, ae3,
                                    alphab, srcb, offb);
    gat_aggr<false><<<dim3(4, NGRAPH), 256>>>(bufA, alphab, srcb, offb, b3,
                                              bufB, nullptr, nullptr);
    // pooling + agent rows -> GRU GEMM operand (hi/lo), then GI GEMM
    pool_k<<<dim3(NGRAPH, FDIM / 128), 128>>>(bufB, Ah, Al);
    agent_k<<<NGRAPH * NA, 128>>>(bufB, Ah, Al);
    splitT_k<<<(GRUI * G3 + 255) / 256, 256>>>(Wih, Bh, Bl, GRUI, G3);
    gemm_mma<<<dim3(G3 / 128, (NGRAPH * NA) / 128), 256, GEMM_SMEM>>>(
        Ah, Al, Bh, Bl, GI, NGRAPH * NA, G3, GRUI);
    // GRU recurrence (10-launch — unchanged from the R8 win)
    cudaMemcpyAsync(h0b, hid0, (size_t)NGRAPH * GRUH * sizeof(float),
                    cudaMemcpyDeviceToDevice);
    for (int t = 0; t < NA; t++) {
        float* hc = (t & 1) ? h1b : h0b;
        float* hn = (t & 1) ? h0b : h1b;
        gru_gh_k<<<NGRAPH / 8, G3>>>(hc, Whh, GHb);
        gru_gate_k<<<NGRAPH, GRUH>>>(GI, t, GHb, hc, bih, bhh, hn, gout,
                                     (t == NA - 1) ? (out + NGRAPH * NA * 3 * 2) : nullptr);
    }
    fc_k<<<NGRAPH * NA, 64>>>(gout, fc1W, fc1b, fc2W, fc2b, logstd, out);
}

// round 10
// speedup vs baseline: 1.5868x; 1.1730x over previous
#include <cuda_runtime.h>
#include <cuda_fp16.h>
#include <cstdint>

#define NODES 50
#define EPG   400
#define NGRAPH 512
#define NN    (NGRAPH*NODES)   // 25600
#define NE    (NGRAPH*EPG)     // 204800
#define FDIM  512
#define HEADS 8
#define CH    64
#define NA    5
#define GRUH  128
#define GRUI  1024
#define G3    384
#define EMAX  456              // padded per-graph edge capacity (450 used)

// ---------------- scratch (static device globals; no allocation) ----------------
__device__ float g_bufA[NN*FDIM];
__device__ float g_bufB[NN*FDIM];
__device__ __half g_Ah[NN*FDIM];
__device__ __half g_Bh[GRUI*G3 > FDIM*FDIM ? GRUI*G3 : FDIM*FDIM];
__device__ __half g_Bl[GRUI*G3 > FDIM*FDIM ? GRUI*G3 : FDIM*FDIM];
__device__ float g_alpha[NGRAPH*EMAX*HEADS];
__device__ int   g_srcb[NGRAPH*EMAX];
__device__ int   g_offb[NGRAPH*51];
__device__ float g_GI[NGRAPH*NA*G3];
__device__ float g_GHbuf[NGRAPH*G3];
__device__ float g_h0[NGRAPH*GRUH];
__device__ float g_h1[NGRAPH*GRUH];
__device__ float g_gruout[NGRAPH*NA*GRUH];

// ---------------- helpers ----------------
__device__ __forceinline__ uint32_t smem_u32(const void* p) {
    uint32_t a;
    asm("{ .reg .u64 t; cvta.to.shared.u64 t, %1; cvt.u32.u64 %0, t; }" : "=r"(a) : "l"(p));
    return a;
}
__device__ __forceinline__ void cp16(uint32_t sdst, const void* gsrc) {
    asm volatile("cp.async.cg.shared.global [%0], [%1], 16;" :: "r"(sdst), "l"(gsrc) : "memory");
}
__device__ __forceinline__ uint32_t lds32(uint32_t a) {
    uint32_t v;
    asm volatile("ld.shared.b32 %0, [%1];" : "=r"(v) : "r"(a));
    return v;
}
__device__ __forceinline__ void mma16816h(float* c, uint32_t a0, uint32_t a1,
                                          uint32_t a2, uint32_t a3,
                                          uint32_t b0, uint32_t b1) {
    asm volatile(
        "mma.sync.aligned.m16n8k16.row.col.f32.f16.f16.f32 "
        "{%0,%1,%2,%3}, {%4,%5,%6,%7}, {%8,%9}, {%0,%1,%2,%3};"
        : "+f"(c[0]), "+f"(c[1]), "+f"(c[2]), "+f"(c[3])
        : "r"(a0), "r"(a1), "r"(a2), "r"(a3), "r"(b0), "r"(b1));
}
__device__ __forceinline__ void split1h(float v, __half& h, __half& l) {
    h = __float2half_rn(v);
    l = __float2half_rn(v - __half2float(h));
}

// W [K,N] fp32 -> Wt [N,K] fp16 hi/lo (transposed)
__global__ void splitT_k(const float* __restrict__ W, __half* __restrict__ hi,
                         __half* __restrict__ lo, int K, int N) {
    int idx = blockIdx.x * 256 + threadIdx.x;
    if (idx >= N * K) return;
    int n = idx / K, k = idx - n * K;
    float v = W[(size_t)k * N + n];
    __half h, l;
    split1h(v, h, l);
    hi[idx] = h;
    lo[idx] = l;
}

// ---------------- HMMA fp16 2-term GEMM: C[M,N] = A[M,K] * B[N,K]^T --------------
// A single fp16; B hi/lo fp16. C = Ah*Bh + Ah*Bl.
#define STAGES 3
#define PITCH 80
#define MAT_BYTES (128*PITCH)
#define STAGE_BYTES (3*MAT_BYTES)        // A | Bh | Bl
#define GEMM_SMEM (STAGES*STAGE_BYTES)   // 92160

__global__ void __launch_bounds__(256) gemm_mma(
    const __half* __restrict__ A,
    const __half* __restrict__ Bh, const __half* __restrict__ Bl,
    float* __restrict__ C, int M, int N, int K) {
    extern __shared__ char sm8[];
    const uint32_t sb = smem_u32(sm8);
    const int tid = threadIdx.x;
    const int lane = tid & 31, wid = tid >> 5;
    const int wm = wid & 3, wn = wid >> 2;
    const int bm = blockIdx.y * 128, bn = blockIdx.x * 128;
    const int g = lane >> 2, tig = lane & 3;
    const int NCH = K >> 5;

    const char* pA  = (const char*)A;
    const char* pBh = (const char*)Bh;
    const char* pBl = (const char*)Bl;
    const size_t rowb = (size_t)K * 2;

    auto load_stage = [&](int kc, int s) {
        uint32_t sbase = sb + s * STAGE_BYTES;
        size_t kb = (size_t)kc * 64;
#pragma unroll
        for (int i = tid; i < 512; i += 256) {
            int r = i >> 2, gg = i & 3;
            uint32_t so = sbase + r * PITCH + gg * 16;
            size_t ga = (size_t)(bm + r) * rowb + kb + gg * 16;
            size_t gb = (size_t)(bn + r) * rowb + kb + gg * 16;
            cp16(so,               pA  + ga);
            cp16(so + MAT_BYTES,   pBh + gb);
            cp16(so + 2*MAT_BYTES, pBl + gb);
        }
        asm volatile("cp.async.commit_group;" ::: "memory");
    };

    float acc[2][8][4];
#pragma unroll
    for (int f = 0; f < 2; f++)
#pragma unroll
        for (int nf = 0; nf < 8; nf++)
#pragma unroll
            for (int c = 0; c < 4; c++) acc[f][nf][c] = 0.f;

    load_stage(0, 0);
    load_stage(1, 1);

    for (int kc = 0; kc < NCH; kc++) {
        int s = kc % STAGES;
        asm volatile("cp.async.wait_group 1;" ::: "memory");
        __syncthreads();
        if (kc + 2 < NCH) load_stage(kc + 2, (kc + 2) % STAGES);
        else asm volatile("cp.async.commit_group;" ::: "memory");

        uint32_t aA = sb + s * STAGE_BYTES;
        uint32_t aB = aA + MAT_BYTES;
#pragma unroll
        for (int kk = 0; kk < 2; kk++) {
            const uint32_t kof = kk * 32 + tig * 4;
            uint32_t ah[2][4];
#pragma unroll
            for (int f = 0; f < 2; f++) {
                uint32_t r0 = (uint32_t)(wm * 32 + f * 16 + g) * PITCH + kof;
                ah[f][0] = lds32(aA + r0);
                ah[f][1] = lds32(aA + r0 + 8*PITCH);
                ah[f][2] = lds32(aA + r0 + 16);
                ah[f][3] = lds32(aA + r0 + 8*PITCH + 16);
            }
#pragma unroll
            for (int nf = 0; nf < 8; nf++) {
                uint32_t n0 = (uint32_t)(wn * 64 + nf * 8 + g) * PITCH + kof;
                uint32_t bh0 = lds32(aB + n0);
                uint32_t bh1 = lds32(aB + n0 + 16);
                uint32_t bl0 = lds32(aB + MAT_BYTES + n0);
                uint32_t bl1 = lds32(aB + MAT_BYTES + n0 + 16);
#pragma unroll
                for (int f = 0; f < 2; f++) {
                    mma16816h(acc[f][nf], ah[f][0], ah[f][1], ah[f][2], ah[f][3], bh0, bh1);
                    mma16816h(acc[f][nf], ah[f][0], ah[f][1], ah[f][2], ah[f][3], bl0, bl1);
                }
            }
        }
        __syncthreads();
    }

#pragma unroll
    for (int f = 0; f < 2; f++) {
        int r0 = bm + wm * 32 + f * 16 + g;
#pragma unroll
        for (int nf = 0; nf < 8; nf++) {
            int c0 = bn + wn * 64 + nf * 8 + 2 * tig;
            *(float2*)&C[(size_t)r0 * N + c0]       = make_float2(acc[f][nf][0], acc[f][nf][1]);
            *(float2*)&C[(size_t)(r0 + 8) * N + c0] = make_float2(acc[f][nf][2], acc[f][nf][3]);
        }
    }
}

// ---------------- x @ W1  (K=4) ----------------
__global__ void lin1_k(const float* __restrict__ x, const float* __restrict__ W,
                       float* __restrict__ out) {
    int idx = blockIdx.x * 256 + threadIdx.x;
    int n = idx >> 9, f = idx & 511;
    const float* xr = x + n * 4;
    out[idx] = xr[0]*W[f] + xr[1]*W[512+f] + xr[2]*W[1024+f] + xr[3]*W[1536+f];
}

// ---------------- GAT kernel A: attention (per graph, small smem, hi occ) --------
template <bool LOOPS>
__global__ void __launch_bounds__(256) gat_attn(
    const float* __restrict__ hpre,
    const int* __restrict__ esrc, const int* __restrict__ edst,
    const float* __restrict__ ea,
    const float* __restrict__ a_src, const float* __restrict__ a_dst,
    const float* __restrict__ We, const float* __restrict__ ae,
    float* __restrict__ galpha, int* __restrict__ gsrcb, int* __restrict__ goffb) {
    __shared__ float sh_ssrc[400];
    __shared__ float sh_sdst[400];
    __shared__ float sh_alS[EMAX*8];
    __shared__ float sh_den[400];
    __shared__ float sh_av[1024];
    __shared__ float sh_weae[8];
    __shared__ float sh_easum[52];
    __shared__ int   sh_amaxi[400];
    __shared__ int   sh_srcS[EMAX];
    __shared__ int   sh_dstS[EMAX];
    __shared__ int   sh_cnt[52];
    __shared__ int   sh_off[52];
    __shared__ int   sh_cur[52];

    const int g = blockIdx.x;
    const int nb = g * NODES;
    const int eb = g * EPG;
    const int tid = threadIdx.x;
    const int lane = tid & 31, wid = tid >> 5;
    const int ECNT = LOOPS ? (EPG + NODES) : EPG;

    for (int i = tid; i < 400; i += 256) { sh_den[i] = 0.f; sh_amaxi[i] = 0; }
    if (tid < NODES) { sh_cnt[tid] = 0; sh_easum[tid] = 0.f; sh_cur[tid] = 0; }
    for (int i = tid; i < 512; i += 256) {
        sh_av[i] = a_src[i];
        sh_av[512 + i] = a_dst[i];
    }
    if (tid < 8) {
        float s = 0.f;
#pragma unroll
        for (int c = 0; c < 64; c++) s += We[tid * 64 + c] * ae[tid * 64 + c];
        sh_weae[tid] = s;
    }
    __syncthreads();

    for (int e = tid; e < EPG; e += 256) {
        int d = edst[eb + e] - nb;
        atomicAdd(&sh_cnt[d], 1);
        atomicAdd(&sh_easum[d], ea[eb + e]);
    }
    __syncthreads();

    // per-(node,head) scores: warp per node, h read from global once
    for (int n = wid; n < NODES; n += 8) {
        const float4* hr = (const float4*)(hpre + (size_t)(nb + n) * FDIM);
#pragma unroll
        for (int k = 0; k < 4; k++) {
            float4 v = hr[lane + 32 * k];
            int f = 4 * lane + 128 * k;
            float4 as = *(const float4*)(sh_av + f);
            float4 ad = *(const float4*)(sh_av + 512 + f);
            float s1 = v.x*as.x + v.y*as.y + v.z*as.z + v.w*as.w;
            float s2 = v.x*ad.x + v.y*ad.y + v.z*ad.z + v.w*ad.w;
#pragma unroll
            for (int o = 8; o > 0; o >>= 1) {
                s1 += __shfl_xor_sync(0xffffffffu, s1, o);
                s2 += __shfl_xor_sync(0xffffffffu, s2, o);
            }
            if ((lane & 15) == 0) {
                int head = 2 * k + (lane >> 4);
                sh_ssrc[n * 8 + head] = s1;
                sh_sdst[n * 8 + head] = s2;
            }
        }
    }
    __syncthreads();

    if (tid == 0) {
        int o = 0;
        for (int n = 0; n < NODES; n++) { sh_off[n] = o; o += sh_cnt[n] + (LOOPS ? 1 : 0); }
    }
    __syncthreads();

    for (int e = tid; e < ECNT; e += 256) {
        int sl, dl; float eav;
        if (e < EPG) { sl = esrc[eb + e] - nb; dl = edst[eb + e] - nb; eav = ea[eb + e]; }
        else { sl = dl = e - EPG; eav = sh_easum[dl] / fmaxf((float)sh_cnt[dl], 1.f); }
        int pos = sh_off[dl] + atomicAdd(&sh_cur[dl], 1);
        sh_srcS[pos] = sl; sh_dstS[pos] = dl;
#pragma unroll
        for (int h = 0; h < 8; h++) {
            float al = sh_ssrc[sl * 8 + h] + sh_sdst[dl * 8 + h] + eav * sh_weae[h];
            al = al > 0.f ? al : 0.2f * al;
            sh_alS[pos * 8 + h] = al;
            atomicMax(&sh_amaxi[dl * 8 + h], __float_as_int(al));
        }
    }
    __syncthreads();

    for (int i = tid; i < ECNT; i += 256) {
        int dl = sh_dstS[i];
#pragma unroll
        for (int h = 0; h < 8; h++) {
            float p = expf(sh_alS[i * 8 + h] - __int_as_float(sh_amaxi[dl * 8 + h]));
            sh_alS[i * 8 + h] = p;
            atomicAdd(&sh_den[dl * 8 + h], p);
        }
    }
    __syncthreads();
    for (int i = tid; i < 400; i += 256) sh_den[i] = 1.f / (sh_den[i] + 1e-16f);
    __syncthreads();

    // write normalized alpha + sorted src + offsets to global scratch
    float* ga = galpha + (size_t)g * EMAX * 8;
    int* gs = gsrcb + (size_t)g * EMAX;
    for (int i = tid; i < ECNT; i += 256) {
        int dl = sh_dstS[i];
        float4 o0, o1;
        o0.x = sh_alS[i*8+0] * sh_den[dl*8+0];
        o0.y = sh_alS[i*8+1] * sh_den[dl*8+1];
        o0.z = sh_alS[i*8+2] * sh_den[dl*8+2];
        o0.w = sh_alS[i*8+3] * sh_den[dl*8+3];
        o1.x = sh_alS[i*8+4] * sh_den[dl*8+4];
        o1.y = sh_alS[i*8+5] * sh_den[dl*8+5];
        o1.z = sh_alS[i*8+6] * sh_den[dl*8+6];
        o1.w = sh_alS[i*8+7] * sh_den[dl*8+7];
        ((float4*)(ga + i * 8))[0] = o0;
        ((float4*)(ga + i * 8))[1] = o1;
        gs[i] = sh_srcS[i];
    }
    if (tid < NODES) goffb[g * 51 + tid] = sh_off[tid];
    if (tid == NODES) goffb[g * 51 + NODES] = ECNT;
}

// ---------------- GAT kernel B: aggregation (graph x 128-feature slice) ----------
// OUTFP16: write single fp16 (feeds next GEMM A operand) instead of fp32
template <bool OUTFP16>
__global__ void __launch_bounds__(256) gat_aggr(
    const float* __restrict__ hpre,
    const float* __restrict__ galpha, const int* __restrict__ gsrcb,
    const int* __restrict__ goffb,
    const float* __restrict__ bias, float* __restrict__ xout,
    __half* __restrict__ outh) {
    __shared__ float sh_hs[NODES * 128];   // 25.6 KB
    __shared__ float sh_al[EMAX * 2];
    __shared__ int   sh_src[EMAX];
    __shared__ int   sh_off[51];

    const int sl = blockIdx.x;     // 0..3
    const int g = blockIdx.y;
    const int nb = g * NODES;
    const int tid = threadIdx.x;
    const int f = tid & 127, half = tid >> 7;
    const int ECNT = goffb[g * 51 + NODES];

    for (int i = tid; i < NODES * 128; i += 256) {
        int n = i >> 7, ff = i & 127;
        sh_hs[i] = hpre[(size_t)(nb + n) * FDIM + sl * 128 + ff];
    }
    const float* ga = galpha + (size_t)g * EMAX * 8 + sl * 2;
    const int* gs = gsrcb + (size_t)g * EMAX;
    for (int i = tid; i < ECNT; i += 256) {
        sh_al[i * 2]     = ga[i * 8];
        sh_al[i * 2 + 1] = ga[i * 8 + 1];
        sh_src[i] = gs[i];
    }
    if (tid <= NODES) sh_off[tid] = goffb[g * 51 + tid];
    __syncthreads();

    const int hsel = f >> 6;
    const float bv = bias[sl * 128 + f];
    for (int n = half; n < NODES; n += 2) {
        float acc = 0.f;
        const int beg = sh_off[n], end = sh_off[n + 1];
        for (int j = beg; j < end; j++)
            acc += sh_al[j * 2 + hsel] * sh_hs[sh_src[j] * 128 + f];
        float v = fmaxf(acc + bv, 0.f);
        size_t idx = (size_t)(nb + n) * FDIM + sl * 128 + f;
        if (OUTFP16) {
            outh[idx] = __float2half_rn(v);
        } else {
            xout[idx] = v;
        }
    }
}

// ---------------- mean pool -> fp16 graph-emb half of GRU operand ----------------
__global__ void pool_k(const float* __restrict__ x3, __half* __restrict__ Ah) {
    int b = blockIdx.x;
    int f = blockIdx.y * 128 + threadIdx.x;
    float s = 0.f;
#pragma unroll 10
    for (int n = 0; n < NODES; n++) s += x3[(size_t)(b * NODES + n) * FDIM + f];
    s *= (1.f / 50.f);
    __half h = __float2half_rn(s);
#pragma unroll
    for (int t = 0; t < NA; t++)
        Ah[(size_t)(b * NA + t) * GRUI + 512 + f] = h;
}

// ---------------- agent rows -> fp16 agent half of GRU operand -------------------
__global__ void agent_k(const float* __restrict__ x3, __half* __restrict__ Ah) {
    int r = blockIdx.x;           // b*5 + t
    int b = r / 5, t = r - b * 5;
    for (int f = threadIdx.x; f < 512; f += 128)
        Ah[(size_t)r * GRUI + f] =
            __float2half_rn(x3[(size_t)(b * NODES + t) * FDIM + f]);
}

// ---------------- GRU: GH = h @ Whh ----------------
__global__ void gru_gh_k(const float* __restrict__ h, const float* __restrict__ Whh,
                         float* __restrict__ GH) {
    __shared__ float hs[8 * GRUH];
    int b0 = blockIdx.x * 8;
    int tid = threadIdx.x;
    for (int i = tid; i < 8 * GRUH; i += 384) hs[i] = h[b0 * GRUH + i];
    __syncthreads();
    float acc[8];
#pragma unroll
    for (int r = 0; r < 8; r++) acc[r] = 0.f;
    for (int k = 0; k < GRUH; k++) {
        float w = Whh[k * G3 + tid];
#pragma unroll
        for (int r = 0; r < 8; r++) acc[r] += hs[r * GRUH + k] * w;
    }
#pragma unroll
    for (int r = 0; r < 8; r++) GH[(b0 + r) * G3 + tid] = acc[r];
}

// ---------------- GRU gate math ----------------
__global__ void gru_gate_k(const float* __restrict__ GI, int t,
                           const float* __restrict__ GHb, const float* __restrict__ hprev,
                           const float* __restrict__ bih, const float* __restrict__ bhh,
                           float* __restrict__ hnew, float* __restrict__ gout,
                           float* __restrict__ hlast) {
    int b = blockIdx.x, j = threadIdx.x;
    const float* gi = GI + (size_t)(b * NA + t) * G3;
    const float* gh = GHb + (size_t)b * G3;
    float ir = gi[j] + bih[j];
    float iz = gi[j + 128] + bih[j + 128];
    float in_ = gi[j + 256] + bih[j + 256];
    float hr = gh[j] + bhh[j];
    float hz = gh[j + 128] + bhh[j + 128];
    float hn = gh[j + 256] + bhh[j + 256];
    float r = 1.f / (1.f + expf(-(ir + hr)));
    float z = 1.f / (1.f + expf(-(iz + hz)));
    float nn = tanhf(in_ + r * hn);
    float hp = hprev[b * GRUH + j];
    float h = (1.f - z) * nn + z * hp;
    hnew[b * GRUH + j] = h;
    gout[(size_t)(b * NA + t) * GRUH + j] = h;
    if (hlast) hlast[b * GRUH + j] = h;
}

// ---------------- FC head ----------------
__global__ void fc_k(const float* __restrict__ gout, const float* __restrict__ W1,
                     const float* __restrict__ b1, const float* __restrict__ W2,
                     const float* __restrict__ b2, const float* __restrict__ ls,
                     float* __restrict__ out) {
    __shared__ float g[128];
    __shared__ float f1[64];
    int r = blockIdx.x, tid = threadIdx.x;
    g[tid] = gout[(size_t)r * GRUH + tid];
    g[tid + 64] = gout[(size_t)r * GRUH + tid + 64];
    __syncthreads();
    float acc = b1[tid];
#pragma unroll 8
    for (int k = 0; k < 128; k++) acc += g[k] * W1[k * 64 + tid];
    f1[tid] = acc > 0.f ? acc : 0.f;
    __syncthreads();
    if (tid < 3) {
        float a2 = b2[tid];
#pragma unroll
        for (int k = 0; k < 64; k++) a2 += f1[k] * W2[k * 3 + tid];
        out[r * 3 + tid] = a2;
        float l = ls[tid];
        l = fminf(fmaxf(l, -20.f), 2.f);
        out[NGRAPH * NA * 3 + r * 3 + tid] = expf(l);
    }
}

// ---------------- launch ----------------
extern "C" void kernel_launch(void* const* d_in, const int* in_sizes, int n_in,
                              void* d_out, int out_size) {
    const float* x      = (const float*)d_in[0];
    const int*   ei     = (const int*)d_in[1];
    const float* ea     = (const float*)d_in[2];
    const float* hid0   = (const float*)d_in[3];
    const float* W1     = (const float*)d_in[4];
    const float* a_s1   = (const float*)d_in[5];
    const float* a_d1   = (const float*)d_in[6];
    const float* We1    = (const float*)d_in[7];
    const float* ae1    = (const float*)d_in[8];
    const float* b1     = (const float*)d_in[9];
    const float* W2     = (const float*)d_in[10];
    const float* a_s2   = (const float*)d_in[11];
    const float* a_d2   = (const float*)d_in[12];
    const float* We2    = (const float*)d_in[13];
    const float* ae2    = (const float*)d_in[14];
    const float* b2     = (const float*)d_in[15];
    const float* W3     = (const float*)d_in[16];
    const float* a_s3   = (const float*)d_in[17];
    const float* a_d3   = (const float*)d_in[18];
    const float* We3    = (const float*)d_in[19];
    const float* ae3    = (const float*)d_in[20];
    const float* b3     = (const float*)d_in[21];
    const float* Wih    = (const float*)d_in[22];
    const float* Whh    = (const float*)d_in[23];
    const float* bih    = (const float*)d_in[24];
    const float* bhh    = (const float*)d_in[25];
    const float* fc1W   = (const float*)d_in[26];
    const float* fc1b   = (const float*)d_in[27];
    const float* fc2W   = (const float*)d_in[28];
    const float* fc2b   = (const float*)d_in[29];
    const float* logstd = (const float*)d_in[30];
    float* out = (float*)d_out;

    float *bufA, *bufB, *GI, *GHb, *h0b, *h1b, *gout, *alphab;
    int *srcb, *offb;
    __half *Ah, *Bh, *Bl;
    cudaGetSymbolAddress((void**)&bufA, g_bufA);
    cudaGetSymbolAddress((void**)&bufB, g_bufB);
    cudaGetSymbolAddress((void**)&GI,   g_GI);
    cudaGetSymbolAddress((void**)&GHb,  g_GHbuf);
    cudaGetSymbolAddress((void**)&h0b,  g_h0);
    cudaGetSymbolAddress((void**)&h1b,  g_h1);
    cudaGetSymbolAddress((void**)&gout, g_gruout);
    cudaGetSymbolAddress((void**)&alphab, g_alpha);
    cudaGetSymbolAddress((void**)&srcb, g_srcb);
    cudaGetSymbolAddress((void**)&offb, g_offb);
    cudaGetSymbolAddress((void**)&Ah, g_Ah);
    cudaGetSymbolAddress((void**)&Bh, g_Bh);
    cudaGetSymbolAddress((void**)&Bl, g_Bl);

    cudaFuncSetAttribute((const void*)gemm_mma,
                         cudaFuncAttributeMaxDynamicSharedMemorySize, GEMM_SMEM);

    const int* esrc = ei;
    const int* edst = ei + NE;

    // layer 1 -> fp16 A operand directly
    lin1_k<<<(NN * FDIM) / 256, 256>>>(x, W1, bufA);
    gat_attn<false><<<NGRAPH, 256>>>(bufA, esrc, edst, ea, a_s1, a_d1, We1, ae1,
                                     alphab, srcb, offb);
    gat_aggr<true><<<dim3(4, NGRAPH), 256>>>(bufA, alphab, srcb, offb, b1,
                                             nullptr, Ah);
    // layer 2
    splitT_k<<<(FDIM * FDIM + 255) / 256, 256>>>(W2, Bh, Bl, FDIM, FDIM);
    gemm_mma<<<dim3(FDIM / 128, NN / 128), 256, GEMM_SMEM>>>(Ah, Bh, Bl, bufA,
                                                             NN, FDIM, FDIM);
    gat_attn<true><<<NGRAPH, 256>>>(bufA, esrc, edst, ea, a_s2, a_d2, We2, ae2,
                                    alphab, srcb, offb);
    gat_aggr<true><<<dim3(4, NGRAPH), 256>>>(bufA, alphab, srcb, offb, b2,
                                             nullptr, Ah);
    // layer 3 -> fp32 (feeds pool/agent)
    splitT_k<<<(FDIM * FDIM + 255) / 256, 256>>>(W3, Bh, Bl, FDIM, FDIM);
    gemm_mma<<<dim3(FDIM / 128, NN / 128), 256, GEMM_SMEM>>>(Ah, Bh, Bl, bufA,
                                                             NN, FDIM, FDIM);
    gat_attn<true><<<NGRAPH, 256>>>(bufA, esrc, edst, ea, a_s3, a_d3, We3, ae3,
                                    alphab, srcb, offb);
    gat_aggr<false><<<dim3(4, NGRAPH), 256>>>(bufA, alphab, srcb, offb, b3,
                                              bufB, nullptr);
    // pooling + agent rows -> GRU GEMM A operand (fp16), then GI GEMM
    pool_k<<<dim3(NGRAPH, FDIM / 128), 128>>>(bufB, Ah);
    agent_k<<<NGRAPH * NA, 128>>>(bufB, Ah);
    splitT_k<<<(GRUI * G3 + 255) / 256, 256>>>(Wih, Bh, Bl, GRUI, G3);
    gemm_mma<<<dim3(G3 / 128, (NGRAPH * NA) / 128), 256, GEMM_SMEM>>>(
        Ah, Bh, Bl, GI, NGRAPH * NA, G3, GRUI);
    // GRU recurrence (10-launch — unchanged)
    cudaMemcpyAsync(h0b, hid0, (size_t)NGRAPH * GRUH * sizeof(float),
                    cudaMemcpyDeviceToDevice);
    for (int t = 0; t < NA; t++) {
        float* hc = (t & 1) ? h1b : h0b;
        float* hn = (t & 1) ? h0b : h1b;
        gru_gh_k<<<NGRAPH / 8, G3>>>(hc, Whh, GHb);
        gru_gate_k<<<NGRAPH, GRUH>>>(GI, t, GHb, hc, bih, bhh, hn, gout,
                                     (t == NA - 1) ? (out + NGRAPH * NA * 3 * 2) : nullptr);
    }
    fc_k<<<NGRAPH * NA, 64>>>(gout, fc1W, fc1b, fc2W, fc2b, logstd, out);
}

// round 11
// speedup vs baseline: 1.8400x; 1.1596x over previous
#include <cuda_runtime.h>
#include <cuda_fp16.h>
#include <cstdint>

#define NODES 50
#define EPG   400
#define NGRAPH 512
#define NN    (NGRAPH*NODES)   // 25600
#define NE    (NGRAPH*EPG)     // 204800
#define FDIM  512
#define HEADS 8
#define CH    64
#define NA    5
#define GRUH  128
#define GRUI  1024
#define G3    384
#define EMAX  456              // padded per-graph edge capacity (450 used)

// ---------------- scratch (static device globals; no allocation) ----------------
__device__ float g_bufA[NN*FDIM];
__device__ float g_bufB[NN*FDIM];
__device__ __half g_Ah[NN*FDIM];
__device__ __half g_Bh[GRUI*G3 > FDIM*FDIM ? GRUI*G3 : FDIM*FDIM];
__device__ float g_alpha[NGRAPH*EMAX*HEADS];
__device__ int   g_srcb[NGRAPH*EMAX];
__device__ int   g_offb[NGRAPH*51];
__device__ float g_GI[NGRAPH*NA*G3];
__device__ float g_GHbuf[NGRAPH*G3];
__device__ float g_h0[NGRAPH*GRUH];
__device__ float g_h1[NGRAPH*GRUH];
__device__ float g_gruout[NGRAPH*NA*GRUH];

// ---------------- helpers ----------------
__device__ __forceinline__ uint32_t smem_u32(const void* p) {
    uint32_t a;
    asm("{ .reg .u64 t; cvta.to.shared.u64 t, %1; cvt.u32.u64 %0, t; }" : "=r"(a) : "l"(p));
    return a;
}
__device__ __forceinline__ void cp16(uint32_t sdst, const void* gsrc) {
    asm volatile("cp.async.cg.shared.global [%0], [%1], 16;" :: "r"(sdst), "l"(gsrc) : "memory");
}
__device__ __forceinline__ uint32_t lds32(uint32_t a) {
    uint32_t v;
    asm volatile("ld.shared.b32 %0, [%1];" : "=r"(v) : "r"(a));
    return v;
}
__device__ __forceinline__ void mma16816h(float* c, uint32_t a0, uint32_t a1,
                                          uint32_t a2, uint32_t a3,
                                          uint32_t b0, uint32_t b1) {
    asm volatile(
        "mma.sync.aligned.m16n8k16.row.col.f32.f16.f16.f32 "
        "{%0,%1,%2,%3}, {%4,%5,%6,%7}, {%8,%9}, {%0,%1,%2,%3};"
        : "+f"(c[0]), "+f"(c[1]), "+f"(c[2]), "+f"(c[3])
        : "r"(a0), "r"(a1), "r"(a2), "r"(a3), "r"(b0), "r"(b1));
}

// W [K,N] fp32 -> Wt [N,K] fp16 (transposed convert)
__global__ void convT_k(const float* __restrict__ W, __half* __restrict__ hi,
                        int K, int N) {
    int idx = blockIdx.x * 256 + threadIdx.x;
    if (idx >= N * K) return;
    int n = idx / K, k = idx - n * K;
    hi[idx] = __float2half_rn(W[(size_t)k * N + n]);
}

// ---------------- HMMA fp16 GEMM: C[M,N] = A[M,K] * B[N,K]^T ---------------------
// A and B single fp16, fp32 accumulate.
#define STAGES 3
#define PITCH 80
#define MAT_BYTES (128*PITCH)
#define STAGE_BYTES (2*MAT_BYTES)        // A | B
#define GEMM_SMEM (STAGES*STAGE_BYTES)   // 61440

__global__ void __launch_bounds__(256) gemm_mma(
    const __half* __restrict__ A, const __half* __restrict__ B,
    float* __restrict__ C, int M, int N, int K) {
    extern __shared__ char sm8[];
    const uint32_t sb = smem_u32(sm8);
    const int tid = threadIdx.x;
    const int lane = tid & 31, wid = tid >> 5;
    const int wm = wid & 3, wn = wid >> 2;
    const int bm = blockIdx.y * 128, bn = blockIdx.x * 128;
    const int g = lane >> 2, tig = lane & 3;
    const int NCH = K >> 5;

    const char* pA = (const char*)A;
    const char* pB = (const char*)B;
    const size_t rowb = (size_t)K * 2;

    auto load_stage = [&](int kc, int s) {
        uint32_t sbase = sb + s * STAGE_BYTES;
        size_t kb = (size_t)kc * 64;
#pragma unroll
        for (int i = tid; i < 512; i += 256) {
            int r = i >> 2, gg = i & 3;
            uint32_t so = sbase + r * PITCH + gg * 16;
            size_t ga = (size_t)(bm + r) * rowb + kb + gg * 16;
            size_t gb = (size_t)(bn + r) * rowb + kb + gg * 16;
            cp16(so,             pA + ga);
            cp16(so + MAT_BYTES, pB + gb);
        }
        asm volatile("cp.async.commit_group;" ::: "memory");
    };

    float acc[2][8][4];
#pragma unroll
    for (int f = 0; f < 2; f++)
#pragma unroll
        for (int nf = 0; nf < 8; nf++)
#pragma unroll
            for (int c = 0; c < 4; c++) acc[f][nf][c] = 0.f;

    load_stage(0, 0);
    load_stage(1, 1);

    for (int kc = 0; kc < NCH; kc++) {
        int s = kc % STAGES;
        asm volatile("cp.async.wait_group 1;" ::: "memory");
        __syncthreads();
        if (kc + 2 < NCH) load_stage(kc + 2, (kc + 2) % STAGES);
        else asm volatile("cp.async.commit_group;" ::: "memory");

        uint32_t aA = sb + s * STAGE_BYTES;
        uint32_t aB = aA + MAT_BYTES;
#pragma unroll
        for (int kk = 0; kk < 2; kk++) {
            const uint32_t kof = kk * 32 + tig * 4;
            uint32_t ah[2][4];
#pragma unroll
            for (int f = 0; f < 2; f++) {
                uint32_t r0 = (uint32_t)(wm * 32 + f * 16 + g) * PITCH + kof;
                ah[f][0] = lds32(aA + r0);
                ah[f][1] = lds32(aA + r0 + 8*PITCH);
                ah[f][2] = lds32(aA + r0 + 16);
                ah[f][3] = lds32(aA + r0 + 8*PITCH + 16);
            }
#pragma unroll
            for (int nf = 0; nf < 8; nf++) {
                uint32_t n0 = (uint32_t)(wn * 64 + nf * 8 + g) * PITCH + kof;
                uint32_t bh0 = lds32(aB + n0);
                uint32_t bh1 = lds32(aB + n0 + 16);
#pragma unroll
                for (int f = 0; f < 2; f++)
                    mma16816h(acc[f][nf], ah[f][0], ah[f][1], ah[f][2], ah[f][3], bh0, bh1);
            }
        }
        __syncthreads();
    }

#pragma unroll
    for (int f = 0; f < 2; f++) {
        int r0 = bm + wm * 32 + f * 16 + g;
#pragma unroll
        for (int nf = 0; nf < 8; nf++) {
            int c0 = bn + wn * 64 + nf * 8 + 2 * tig;
            *(float2*)&C[(size_t)r0 * N + c0]       = make_float2(acc[f][nf][0], acc[f][nf][1]);
            *(float2*)&C[(size_t)(r0 + 8) * N + c0] = make_float2(acc[f][nf][2], acc[f][nf][3]);
        }
    }
}

// ---------------- x @ W1  (K=4) ----------------
__global__ void lin1_k(const float* __restrict__ x, const float* __restrict__ W,
                       float* __restrict__ out) {
    int idx = blockIdx.x * 256 + threadIdx.x;
    int n = idx >> 9, f = idx & 511;
    const float* xr = x + n * 4;
    out[idx] = xr[0]*W[f] + xr[1]*W[512+f] + xr[2]*W[1024+f] + xr[3]*W[1536+f];
}

// ---------------- GAT kernel A: attention (per graph, small smem, hi occ) --------
template <bool LOOPS>
__global__ void __launch_bounds__(256) gat_attn(
    const float* __restrict__ hpre,
    const int* __restrict__ esrc, const int* __restrict__ edst,
    const float* __restrict__ ea,
    const float* __restrict__ a_src, const float* __restrict__ a_dst,
    const float* __restrict__ We, const float* __restrict__ ae,
    float* __restrict__ galpha, int* __restrict__ gsrcb, int* __restrict__ goffb) {
    __shared__ float sh_ssrc[400];
    __shared__ float sh_sdst[400];
    __shared__ float sh_alS[EMAX*8];
    __shared__ float sh_den[400];
    __shared__ float sh_av[1024];
    __shared__ float sh_weae[8];
    __shared__ float sh_easum[52];
    __shared__ int   sh_amaxi[400];
    __shared__ int   sh_srcS[EMAX];
    __shared__ int   sh_dstS[EMAX];
    __shared__ int   sh_cnt[52];
    __shared__ int   sh_off[52];
    __shared__ int   sh_cur[52];

    const int g = blockIdx.x;
    const int nb = g * NODES;
    const int eb = g * EPG;
    const int tid = threadIdx.x;
    const int lane = tid & 31, wid = tid >> 5;
    const int ECNT = LOOPS ? (EPG + NODES) : EPG;

    for (int i = tid; i < 400; i += 256) { sh_den[i] = 0.f; sh_amaxi[i] = 0; }
    if (tid < NODES) { sh_cnt[tid] = 0; sh_easum[tid] = 0.f; sh_cur[tid] = 0; }
    for (int i = tid; i < 512; i += 256) {
        sh_av[i] = a_src[i];
        sh_av[512 + i] = a_dst[i];
    }
    if (tid < 8) {
        float s = 0.f;
#pragma unroll
        for (int c = 0; c < 64; c++) s += We[tid * 64 + c] * ae[tid * 64 + c];
        sh_weae[tid] = s;
    }
    __syncthreads();

    for (int e = tid; e < EPG; e += 256) {
        int d = edst[eb + e] - nb;
        atomicAdd(&sh_cnt[d], 1);
        atomicAdd(&sh_easum[d], ea[eb + e]);
    }
    __syncthreads();

    // per-(node,head) scores: warp per node, h read from global once
    for (int n = wid; n < NODES; n += 8) {
        const float4* hr = (const float4*)(hpre + (size_t)(nb + n) * FDIM);
#pragma unroll
        for (int k = 0; k < 4; k++) {
            float4 v = hr[lane + 32 * k];
            int f = 4 * lane + 128 * k;
            float4 as = *(const float4*)(sh_av + f);
            float4 ad = *(const float4*)(sh_av + 512 + f);
            float s1 = v.x*as.x + v.y*as.y + v.z*as.z + v.w*as.w;
            float s2 = v.x*ad.x + v.y*ad.y + v.z*ad.z + v.w*ad.w;
#pragma unroll
            for (int o = 8; o > 0; o >>= 1) {
                s1 += __shfl_xor_sync(0xffffffffu, s1, o);
                s2 += __shfl_xor_sync(0xffffffffu, s2, o);
            }
            if ((lane & 15) == 0) {
                int head = 2 * k + (lane >> 4);
                sh_ssrc[n * 8 + head] = s1;
                sh_sdst[n * 8 + head] = s2;
            }
        }
    }
    __syncthreads();

    if (tid == 0) {
        int o = 0;
        for (int n = 0; n < NODES; n++) { sh_off[n] = o; o += sh_cnt[n] + (LOOPS ? 1 : 0); }
    }
    __syncthreads();

    for (int e = tid; e < ECNT; e += 256) {
        int sl, dl; float eav;
        if (e < EPG) { sl = esrc[eb + e] - nb; dl = edst[eb + e] - nb; eav = ea[eb + e]; }
        else { sl = dl = e - EPG; eav = sh_easum[dl] / fmaxf((float)sh_cnt[dl], 1.f); }
        int pos = sh_off[dl] + atomicAdd(&sh_cur[dl], 1);
        sh_srcS[pos] = sl; sh_dstS[pos] = dl;
#pragma unroll
        for (int h = 0; h < 8; h++) {
            float al = sh_ssrc[sl * 8 + h] + sh_sdst[dl * 8 + h] + eav * sh_weae[h];
            al = al > 0.f ? al : 0.2f * al;
            sh_alS[pos * 8 + h] = al;
            atomicMax(&sh_amaxi[dl * 8 + h], __float_as_int(al));
        }
    }
    __syncthreads();

    for (int i = tid; i < ECNT; i += 256) {
        int dl = sh_dstS[i];
#pragma unroll
        for (int h = 0; h < 8; h++) {
            float p = expf(sh_alS[i * 8 + h] - __int_as_float(sh_amaxi[dl * 8 + h]));
            sh_alS[i * 8 + h] = p;
            atomicAdd(&sh_den[dl * 8 + h], p);
        }
    }
    __syncthreads();
    for (int i = tid; i < 400; i += 256) sh_den[i] = 1.f / (sh_den[i] + 1e-16f);
    __syncthreads();

    // write normalized alpha + sorted src + offsets to global scratch
    float* ga = galpha + (size_t)g * EMAX * 8;
    int* gs = gsrcb + (size_t)g * EMAX;
    for (int i = tid; i < ECNT; i += 256) {
        int dl = sh_dstS[i];
        float4 o0, o1;
        o0.x = sh_alS[i*8+0] * sh_den[dl*8+0];
        o0.y = sh_alS[i*8+1] * sh_den[dl*8+1];
        o0.z = sh_alS[i*8+2] * sh_den[dl*8+2];
        o0.w = sh_alS[i*8+3] * sh_den[dl*8+3];
        o1.x = sh_alS[i*8+4] * sh_den[dl*8+4];
        o1.y = sh_alS[i*8+5] * sh_den[dl*8+5];
        o1.z = sh_alS[i*8+6] * sh_den[dl*8+6];
        o1.w = sh_alS[i*8+7] * sh_den[dl*8+7];
        ((float4*)(ga + i * 8))[0] = o0;
        ((float4*)(ga + i * 8))[1] = o1;
        gs[i] = sh_srcS[i];
    }
    if (tid < NODES) goffb[g * 51 + tid] = sh_off[tid];
    if (tid == NODES) goffb[g * 51 + NODES] = ECNT;
}

// ---------------- GAT kernel B: aggregation (graph x 128-feature slice) ----------
// OUTFP16: write single fp16 (feeds next GEMM A operand) instead of fp32
template <bool OUTFP16>
__global__ void __launch_bounds__(256) gat_aggr(
    const float* __restrict__ hpre,
    const float* __restrict__ galpha, const int* __restrict__ gsrcb,
    const int* __restrict__ goffb,
    const float* __restrict__ bias, float* __restrict__ xout,
    __half* __restrict__ outh) {
    __shared__ float sh_hs[NODES * 128];   // 25.6 KB
    __shared__ float sh_al[EMAX * 2];
    __shared__ int   sh_src[EMAX];
    __shared__ int   sh_off[51];

    const int sl = blockIdx.x;     // 0..3
    const int g = blockIdx.y;
    const int nb = g * NODES;
    const int tid = threadIdx.x;
    const int f = tid & 127, half = tid >> 7;
    const int ECNT = goffb[g * 51 + NODES];

    for (int i = tid; i < NODES * 128; i += 256) {
        int n = i >> 7, ff = i & 127;
        sh_hs[i] = hpre[(size_t)(nb + n) * FDIM + sl * 128 + ff];
    }
    const float* ga = galpha + (size_t)g * EMAX * 8 + sl * 2;
    const int* gs = gsrcb + (size_t)g * EMAX;
    for (int i = tid; i < ECNT; i += 256) {
        sh_al[i * 2]     = ga[i * 8];
        sh_al[i * 2 + 1] = ga[i * 8 + 1];
        sh_src[i] = gs[i];
    }
    if (tid <= NODES) sh_off[tid] = goffb[g * 51 + tid];
    __syncthreads();

    const int hsel = f >> 6;
    const float bv = bias[sl * 128 + f];
    for (int n = half; n < NODES; n += 2) {
        float acc = 0.f;
        const int beg = sh_off[n], end = sh_off[n + 1];
        for (int j = beg; j < end; j++)
            acc += sh_al[j * 2 + hsel] * sh_hs[sh_src[j] * 128 + f];
        float v = fmaxf(acc + bv, 0.f);
        size_t idx = (size_t)(nb + n) * FDIM + sl * 128 + f;
        if (OUTFP16) {
            outh[idx] = __float2half_rn(v);
        } else {
            xout[idx] = v;
        }
    }
}

// ---------------- mean pool -> fp16 graph-emb half of GRU operand ----------------
__global__ void pool_k(const float* __restrict__ x3, __half* __restrict__ Ah) {
    int b = blockIdx.x;
    int f = blockIdx.y * 128 + threadIdx.x;
    float s = 0.f;
#pragma unroll 10
    for (int n = 0; n < NODES; n++) s += x3[(size_t)(b * NODES + n) * FDIM + f];
    s *= (1.f / 50.f);
    __half h = __float2half_rn(s);
#pragma unroll
    for (int t = 0; t < NA; t++)
        Ah[(size_t)(b * NA + t) * GRUI + 512 + f] = h;
}

// ---------------- agent rows -> fp16 agent half of GRU operand -------------------
__global__ void agent_k(const float* __restrict__ x3, __half* __restrict__ Ah) {
    int r = blockIdx.x;           // b*5 + t
    int b = r / 5, t = r - b * 5;
    for (int f = threadIdx.x; f < 512; f += 128)
        Ah[(size_t)r * GRUI + f] =
            __float2half_rn(x3[(size_t)(b * NODES + t) * FDIM + f]);
}

// ---------------- GRU: GH = h @ Whh ----------------
__global__ void gru_gh_k(const float* __restrict__ h, const float* __restrict__ Whh,
                         float* __restrict__ GH) {
    __shared__ float hs[8 * GRUH];
    int b0 = blockIdx.x * 8;
    int tid = threadIdx.x;
    for (int i = tid; i < 8 * GRUH; i += 384) hs[i] = h[b0 * GRUH + i];
    __syncthreads();
    float acc[8];
#pragma unroll
    for (int r = 0; r < 8; r++) acc[r] = 0.f;
    for (int k = 0; k < GRUH; k++) {
        float w = Whh[k * G3 + tid];
#pragma unroll
        for (int r = 0; r < 8; r++) acc[r] += hs[r * GRUH + k] * w;
    }
#pragma unroll
    for (int r = 0; r < 8; r++) GH[(b0 + r) * G3 + tid] = acc[r];
}

// ---------------- GRU gate math ----------------
__global__ void gru_gate_k(const float* __restrict__ GI, int t,
                           const float* __restrict__ GHb, const float* __restrict__ hprev,
                           const float* __restrict__ bih, const float* __restrict__ bhh,
                           float* __restrict__ hnew, float* __restrict__ gout,
                           float* __restrict__ hlast) {
    int b = blockIdx.x, j = threadIdx.x;
    const float* gi = GI + (size_t)(b * NA + t) * G3;
    const float* gh = GHb + (size_t)b * G3;
    float ir = gi[j] + bih[j];
    float iz = gi[j + 128] + bih[j + 128];
    float in_ = gi[j + 256] + bih[j + 256];
    float hr = gh[j] + bhh[j];
    float hz = gh[j + 128] + bhh[j + 128];
    float hn = gh[j + 256] + bhh[j + 256];
    float r = 1.f / (1.f + expf(-(ir + hr)));
    float z = 1.f / (1.f + expf(-(iz + hz)));
    float nn = tanhf(in_ + r * hn);
    float hp = hprev[b * GRUH + j];
    float h = (1.f - z) * nn + z * hp;
    hnew[b * GRUH + j] = h;
    gout[(size_t)(b * NA + t) * GRUH + j] = h;
    if (hlast) hlast[b * GRUH + j] = h;
}

// ---------------- FC head ----------------
__global__ void fc_k(const float* __restrict__ gout, const float* __restrict__ W1,
                     const float* __restrict__ b1, const float* __restrict__ W2,
                     const float* __restrict__ b2, const float* __restrict__ ls,
                     float* __restrict__ out) {
    __shared__ float g[128];
    __shared__ float f1[64];
    int r = blockIdx.x, tid = threadIdx.x;
    g[tid] = gout[(size_t)r * GRUH + tid];
    g[tid + 64] = gout[(size_t)r * GRUH + tid + 64];
    __syncthreads();
    float acc = b1[tid];
#pragma unroll 8
    for (int k = 0; k < 128; k++) acc += g[k] * W1[k * 64 + tid];
    f1[tid] = acc > 0.f ? acc : 0.f;
    __syncthreads();
    if (tid < 3) {
        float a2 = b2[tid];
#pragma unroll
        for (int k = 0; k < 64; k++) a2 += f1[k] * W2[k * 3 + tid];
        out[r * 3 + tid] = a2;
        float l = ls[tid];
        l = fminf(fmaxf(l, -20.f), 2.f);
        out[NGRAPH * NA * 3 + r * 3 + tid] = expf(l);
    }
}

// ---------------- launch ----------------
extern "C" void kernel_launch(void* const* d_in, const int* in_sizes, int n_in,
                              void* d_out, int out_size) {
    const float* x      = (const float*)d_in[0];
    const int*   ei     = (const int*)d_in[1];
    const float* ea     = (const float*)d_in[2];
    const float* hid0   = (const float*)d_in[3];
    const float* W1     = (const float*)d_in[4];
    const float* a_s1   = (const float*)d_in[5];
    const float* a_d1   = (const float*)d_in[6];
    const float* We1    = (const float*)d_in[7];
    const float* ae1    = (const float*)d_in[8];
    const float* b1     = (const float*)d_in[9];
    const float* W2     = (const float*)d_in[10];
    const float* a_s2   = (const float*)d_in[11];
    const float* a_d2   = (const float*)d_in[12];
    const float* We2    = (const float*)d_in[13];
    const float* ae2    = (const float*)d_in[14];
    const float* b2     = (const float*)d_in[15];
    const float* W3     = (const float*)d_in[16];
    const float* a_s3   = (const float*)d_in[17];
    const float* a_d3   = (const float*)d_in[18];
    const float* We3    = (const float*)d_in[19];
    const float* ae3    = (const float*)d_in[20];
    const float* b3     = (const float*)d_in[21];
    const float* Wih    = (const float*)d_in[22];
    const float* Whh    = (const float*)d_in[23];
    const float* bih    = (const float*)d_in[24];
    const float* bhh    = (const float*)d_in[25];
    const float* fc1W   = (const float*)d_in[26];
    const float* fc1b   = (const float*)d_in[27];
    const float* fc2W   = (const float*)d_in[28];
    const float* fc2b   = (const float*)d_in[29];
    const float* logstd = (const float*)d_in[30];
    float* out = (float*)d_out;

    float *bufA, *bufB, *GI, *GHb, *h0b, *h1b, *gout, *alphab;
    int *srcb, *offb;
    __half *Ah, *Bh;
    cudaGetSymbolAddress((void**)&bufA, g_bufA);
    cudaGetSymbolAddress((void**)&bufB, g_bufB);
    cudaGetSymbolAddress((void**)&GI,   g_GI);
    cudaGetSymbolAddress((void**)&GHb,  g_GHbuf);
    cudaGetSymbolAddress((void**)&h0b,  g_h0);
    cudaGetSymbolAddress((void**)&h1b,  g_h1);
    cudaGetSymbolAddress((void**)&gout, g_gruout);
    cudaGetSymbolAddress((void**)&alphab, g_alpha);
    cudaGetSymbolAddress((void**)&srcb, g_srcb);
    cudaGetSymbolAddress((void**)&offb, g_offb);
    cudaGetSymbolAddress((void**)&Ah, g_Ah);
    cudaGetSymbolAddress((void**)&Bh, g_Bh);

    cudaFuncSetAttribute((const void*)gemm_mma,
                         cudaFuncAttributeMaxDynamicSharedMemorySize, GEMM_SMEM);

    const int* esrc = ei;
    const int* edst = ei + NE;

    // layer 1 -> fp16 A operand directly
    lin1_k<<<(NN * FDIM) / 256, 256>>>(x, W1, bufA);
    gat_attn<false><<<NGRAPH, 256>>>(bufA, esrc, edst, ea, a_s1, a_d1, We1, ae1,
                                     alphab, srcb, offb);
    gat_aggr<true><<<dim3(4, NGRAPH), 256>>>(bufA, alphab, srcb, offb, b1,
                                             nullptr, Ah);
    // layer 2
    convT_k<<<(FDIM * FDIM + 255) / 256, 256>>>(W2, Bh, FDIM, FDIM);
    gemm_mma<<<dim3(FDIM / 128, NN / 128), 256, GEMM_SMEM>>>(Ah, Bh, bufA,
                                                             NN, FDIM, FDIM);
    gat_attn<true><<<NGRAPH, 256>>>(bufA, esrc, edst, ea, a_s2, a_d2, We2, ae2,
                                    alphab, srcb, offb);
    gat_aggr<true><<<dim3(4, NGRAPH), 256>>>(bufA, alphab, srcb, offb, b2,
                                             nullptr, Ah);
    // layer 3 -> fp32 (feeds pool/agent)
    convT_k<<<(FDIM * FDIM + 255) / 256, 256>>>(W3, Bh, FDIM, FDIM);
    gemm_mma<<<dim3(FDIM / 128, NN / 128), 256, GEMM_SMEM>>>(Ah, Bh, bufA,
                                                             NN, FDIM, FDIM);
    gat_attn<true><<<NGRAPH, 256>>>(bufA, esrc, edst, ea, a_s3, a_d3, We3, ae3,
                                    alphab, srcb, offb);
    gat_aggr<false><<<dim3(4, NGRAPH), 256>>>(bufA, alphab, srcb, offb, b3,
                                              bufB, nullptr);
    // pooling + agent rows -> GRU GEMM A operand (fp16), then GI GEMM
    pool_k<<<dim3(NGRAPH, FDIM / 128), 128>>>(bufB, Ah);
    agent_k<<<NGRAPH * NA, 128>>>(bufB, Ah);
    convT_k<<<(GRUI * G3 + 255) / 256, 256>>>(Wih, Bh, GRUI, G3);
    gemm_mma<<<dim3(G3 / 128, (NGRAPH * NA) / 128), 256, GEMM_SMEM>>>(
        Ah, Bh, GI, NGRAPH * NA, G3, GRUI);
    // GRU recurrence (10-launch — unchanged)
    cudaMemcpyAsync(h0b, hid0, (size_t)NGRAPH * GRUH * sizeof(float),
                    cudaMemcpyDeviceToDevice);
    for (int t = 0; t < NA; t++) {
        float* hc = (t & 1) ? h1b : h0b;
        float* hn = (t & 1) ? h0b : h1b;
        gru_gh_k<<<NGRAPH / 8, G3>>>(hc, Whh, GHb);
        gru_gate_k<<<NGRAPH, GRUH>>>(GI, t, GHb, hc, bih, bhh, hn, gout,
                                     (t == NA - 1) ? (out + NGRAPH * NA * 3 * 2) : nullptr);
    }
    fc_k<<<NGRAPH * NA, 64>>>(gout, fc1W, fc1b, fc2W, fc2b, logstd, out);
}